// round 1
// baseline (speedup 1.0000x reference)
#include <cuda_runtime.h>
#include <math.h>

#define T_LEN  4096
#define L_LEN  128
#define NF     128      // total filters = C*Kc = 8*16
#define NWIN   3969     // T - L + 1
#define B_SZ   256
#define TW     128      // windows per tile
#define NTILE  32       // ceil(3969/128)
#define FG     64       // filters per block
#define EPSF   1e-6f

// ---- device scratch (no allocations allowed) ----
__device__ float g_snorm[L_LEN * NF];              // [l][f] layout
__device__ float g_scratch[B_SZ * NTILE * NF];     // per-tile maxima

// ---- packed f32x2 helpers (FFMA2 path, ptxas never auto-fuses) ----
__device__ __forceinline__ unsigned long long pack2(float lo, float hi) {
    unsigned long long r;
    asm("mov.b64 %0, {%1, %2};" : "=l"(r) : "f"(lo), "f"(hi));
    return r;
}
__device__ __forceinline__ unsigned long long ffma2(unsigned long long a,
                                                    unsigned long long b,
                                                    unsigned long long c) {
    unsigned long long d;
    asm("fma.rn.f32x2 %0, %1, %2, %3;" : "=l"(d) : "l"(a), "l"(b), "l"(c));
    return d;
}
__device__ __forceinline__ float2 unpack2(unsigned long long v) {
    float2 r;
    asm("mov.b64 {%0, %1}, %2;" : "=f"(r.x), "=f"(r.y) : "l"(v));
    return r;
}

// ============================================================
// Kernel 1: z-normalize shapelets -> g_snorm[l][f]
// ============================================================
__global__ void prep_snorm_kernel(const float* __restrict__ sh) {
    const int f = blockIdx.x;     // 0..127 (flat c*16+k, matches output order)
    const int l = threadIdx.x;    // 0..127
    __shared__ float red[128];

    float v = sh[f * L_LEN + l];
    red[l] = v;
    __syncthreads();
    #pragma unroll
    for (int s = 64; s > 0; s >>= 1) {
        if (l < s) red[l] += red[l + s];
        __syncthreads();
    }
    float mu = red[0] * (1.0f / L_LEN);
    __syncthreads();
    float d = v - mu;
    red[l] = d * d;
    __syncthreads();
    #pragma unroll
    for (int s = 64; s > 0; s >>= 1) {
        if (l < s) red[l] += red[l + s];
        __syncthreads();
    }
    float stdv = sqrtf(red[0] * (1.0f / L_LEN)) + EPSF;
    g_snorm[l * NF + f] = d / stdv;
}

// ============================================================
// Kernel 2: main sliding-correlation. Block = (tile, fgroup, b).
// 256 threads; each thread: 4 windows x 8 filters (16 f32x2 accs).
// ============================================================
__global__ __launch_bounds__(256, 4)
void shapelet_main_kernel(const float* __restrict__ x) {
    const int tile = blockIdx.x;         // 0..31
    const int fg   = blockIdx.y;         // 0..1
    const int b    = blockIdx.z;         // 0..255
    const int tid  = threadIdx.x;
    const int tx   = tid & 7;            // 8 filter groups
    const int ty   = tid >> 3;           // 32 window groups
    const int f0   = tx * 8;             // local filter base (0..56)
    const int w0   = ty * 4;             // local window base (0..124)
    const int t0   = tile * TW;

    __shared__ float s_s[L_LEN][FG];     // 32 KB, [l][f_local]
    __shared__ float x_s[TW + L_LEN];    // 256 floats (need 255)
    __shared__ float wscale[TW];
    __shared__ float red[32][FG];        // 8 KB

    // ---- load x slice (255 valid + 1 pad), zero-fill past T ----
    {
        int t = t0 + tid;
        x_s[tid] = (t < T_LEN) ? x[b * T_LEN + t] : 0.0f;
    }
    // ---- load shapelet tile (vectorized): 2048 float4 / 256 thr = 8 each ----
    {
        const float4* gs  = (const float4*)g_snorm;   // row = 32 float4
        float4*       ss4 = (float4*)s_s;             // row = 16 float4
        #pragma unroll
        for (int k = 0; k < 8; ++k) {
            int idx = tid + k * 256;
            int l = idx >> 4, c = idx & 15;
            ss4[l * 16 + c] = gs[l * 32 + fg * 16 + c];
        }
    }
    __syncthreads();

    // ---- per-window inverse scale: 1 / (L * (std + eps)) ----
    if (tid < TW) {
        float s = 0.0f, s2 = 0.0f;
        #pragma unroll 8
        for (int l = 0; l < L_LEN; ++l) {
            float v = x_s[tid + l];
            s += v;
            s2 = fmaf(v, v, s2);
        }
        float mu  = s * (1.0f / L_LEN);
        float var = fmaxf(s2 * (1.0f / L_LEN) - mu * mu, 0.0f);
        wscale[tid] = 1.0f / ((sqrtf(var) + EPSF) * (float)L_LEN);
    }
    __syncthreads();

    // ---- main FMA loop: 16 f32x2 FMAs per l per thread ----
    unsigned long long acc[4][4];
    #pragma unroll
    for (int i = 0; i < 4; ++i)
        #pragma unroll
        for (int p = 0; p < 4; ++p)
            acc[i][p] = 0ull;

    #pragma unroll 4
    for (int l = 0; l < L_LEN; ++l) {
        float4 sA = *(const float4*)&s_s[l][f0];
        float4 sB = *(const float4*)&s_s[l][f0 + 4];
        unsigned long long sp0 = pack2(sA.x, sA.y);
        unsigned long long sp1 = pack2(sA.z, sA.w);
        unsigned long long sp2 = pack2(sB.x, sB.y);
        unsigned long long sp3 = pack2(sB.z, sB.w);
        #pragma unroll
        for (int i = 0; i < 4; ++i) {
            float xv = x_s[w0 + i + l];
            unsigned long long xx = pack2(xv, xv);
            acc[i][0] = ffma2(sp0, xx, acc[i][0]);
            acc[i][1] = ffma2(sp1, xx, acc[i][1]);
            acc[i][2] = ffma2(sp2, xx, acc[i][2]);
            acc[i][3] = ffma2(sp3, xx, acc[i][3]);
        }
    }

    // ---- epilogue: scale by wscale, max over this thread's 4 windows ----
    float lm[8];
    #pragma unroll
    for (int j = 0; j < 8; ++j) lm[j] = -INFINITY;

    #pragma unroll
    for (int i = 0; i < 4; ++i) {
        if (t0 + w0 + i < NWIN) {
            float sc = wscale[w0 + i];
            #pragma unroll
            for (int p = 0; p < 4; ++p) {
                float2 v = unpack2(acc[i][p]);
                lm[2 * p]     = fmaxf(lm[2 * p],     v.x * sc);
                lm[2 * p + 1] = fmaxf(lm[2 * p + 1], v.y * sc);
            }
        }
    }

    #pragma unroll
    for (int j = 0; j < 8; ++j) red[ty][f0 + j] = lm[j];
    __syncthreads();

    // ---- reduce 32 window-groups -> per-tile max per filter ----
    if (tid < FG) {
        float m = -INFINITY;
        #pragma unroll
        for (int r = 0; r < 32; ++r) m = fmaxf(m, red[r][tid]);
        g_scratch[(b * NTILE + tile) * NF + fg * FG + tid] = m;
    }
}

// ============================================================
// Kernel 3: final max over tiles
// ============================================================
__global__ void reduce_max_kernel(float* __restrict__ out) {
    const int b = blockIdx.x;
    const int f = threadIdx.x;   // 128
    float m = -INFINITY;
    #pragma unroll
    for (int t = 0; t < NTILE; ++t)
        m = fmaxf(m, g_scratch[(b * NTILE + t) * NF + f]);
    out[b * NF + f] = m;
}

extern "C" void kernel_launch(void* const* d_in, const int* in_sizes, int n_in,
                              void* d_out, int out_size) {
    const float* x  = (const float*)d_in[0];   // (256, 4096) fp32
    const float* sh = (const float*)d_in[1];   // (8, 16, 128) fp32
    float* out = (float*)d_out;                // (256, 128) fp32

    prep_snorm_kernel<<<NF, L_LEN>>>(sh);
    dim3 grid(NTILE, 2, B_SZ);
    shapelet_main_kernel<<<grid, 256>>>(x);
    reduce_max_kernel<<<B_SZ, NF>>>(out);
}

// round 4
// speedup vs baseline: 2.4806x; 2.4806x over previous
#include <cuda_runtime.h>
#include <cuda_bf16.h>
#include <math.h>
#include <stdint.h>
#include <string.h>

#define T_LEN   4096
#define L_LEN   128
#define NF      128
#define NWIN    3969
#define B_SZ    256
#define NTILE   16          // 16 tiles x 256 windows = 4096 >= 3969
#define EPSF    1e-6f
#define LDA     136         // padded row stride (elements) -> 272B, conflict-free LDSM

// ---------------- device scratch ----------------
__device__ float    g_scratch[B_SZ * NTILE * NF];
__device__ uint32_t g_sh32[NF * 64];   // s_norm hi bf16x2, [f][k/2]
__device__ uint32_t g_sl32[NF * 64];   // s_norm lo bf16x2

// ---------------- smem layout (bytes) ----------------
#define OFF_AH    0          // 256 x 136 bf16 = 69632
#define OFF_AL    69632
#define OFF_BH    139264     // 128 x 136 bf16 = 34816
#define OFF_BL    174080
#define OFF_XS    208896     // float[384]
#define OFF_XH    210432     // ushort[384]
#define OFF_XL    211200     // ushort[384]
#define OFF_WS    211968     // float[256]
#define OFF_WMAX  212992     // float[4][128]
#define SMEM_DYN  215040

__device__ __forceinline__ uint32_t smem_to_u32(const void* p) {
    uint32_t a;
    asm("{ .reg .u64 t; cvta.to.shared.u64 t, %1; cvt.u32.u64 %0, t; }" : "=r"(a) : "l"(p));
    return a;
}
__device__ __forceinline__ void ldsm_x4(uint32_t* r, uint32_t addr) {
    asm volatile("ldmatrix.sync.aligned.m8n8.x4.shared.b16 {%0,%1,%2,%3}, [%4];"
                 : "=r"(r[0]), "=r"(r[1]), "=r"(r[2]), "=r"(r[3]) : "r"(addr));
}
__device__ __forceinline__ void mma_bf16(float* c, const uint32_t* a, const uint32_t* b) {
    asm volatile(
        "mma.sync.aligned.m16n8k16.row.col.f32.bf16.bf16.f32 "
        "{%0,%1,%2,%3}, {%4,%5,%6,%7}, {%8,%9}, {%0,%1,%2,%3};"
        : "+f"(c[0]), "+f"(c[1]), "+f"(c[2]), "+f"(c[3])
        : "r"(a[0]), "r"(a[1]), "r"(a[2]), "r"(a[3]), "r"(b[0]), "r"(b[1]));
}

// ============================================================
// Kernel 1: z-normalize shapelets, split to bf16 hi/lo words
// ============================================================
__global__ void prep_snorm_kernel(const float* __restrict__ sh) {
    const int f = blockIdx.x;
    const int l = threadIdx.x;
    __shared__ float red[128];
    __shared__ unsigned short th[128], tl[128];

    float v = sh[f * L_LEN + l];
    red[l] = v;
    __syncthreads();
    #pragma unroll
    for (int s = 64; s > 0; s >>= 1) { if (l < s) red[l] += red[l + s]; __syncthreads(); }
    float mu = red[0] * (1.0f / L_LEN);
    __syncthreads();
    float d = v - mu;
    red[l] = d * d;
    __syncthreads();
    #pragma unroll
    for (int s = 64; s > 0; s >>= 1) { if (l < s) red[l] += red[l + s]; __syncthreads(); }
    float stdv = sqrtf(red[0] * (1.0f / L_LEN)) + EPSF;
    float sn = d / stdv;

    __nv_bfloat16 h = __float2bfloat16(sn);
    float hf = __bfloat162float(h);
    __nv_bfloat16 lo = __float2bfloat16(sn - hf);
    unsigned short hu, lu;
    memcpy(&hu, &h, 2);
    memcpy(&lu, &lo, 2);
    th[l] = hu; tl[l] = lu;
    __syncthreads();
    if (l < 64) {
        g_sh32[f * 64 + l] = (uint32_t)th[2 * l] | ((uint32_t)th[2 * l + 1] << 16);
        g_sl32[f * 64 + l] = (uint32_t)tl[2 * l] | ((uint32_t)tl[2 * l + 1] << 16);
    }
}

// ============================================================
// Kernel 2: mma.sync main kernel. CTA = (tile, batch): 256 win x 128 filt.
// 8 warps (4 M-rows x 2 N-cols), warp tile 64x64, 3 bf16 passes.
// ============================================================
__global__ __launch_bounds__(256, 1)
void shapelet_mma_kernel(const float* __restrict__ x) {
    extern __shared__ char smem[];
    const uint32_t sbase = smem_to_u32(smem);

    const int tp  = blockIdx.x;        // 0..15
    const int b   = blockIdx.y;        // 0..255
    const int tid = threadIdx.x;
    const int wid = tid >> 5;
    const int lid = tid & 31;
    const int warpRow = wid >> 1;      // 0..3  (M)
    const int warpCol = wid & 1;       // 0..1  (N)
    const int t0  = tp * 256;

    float*          xs = (float*)(smem + OFF_XS);
    unsigned short* xh = (unsigned short*)(smem + OFF_XH);
    unsigned short* xl = (unsigned short*)(smem + OFF_XL);
    float*          ws = (float*)(smem + OFF_WS);
    float*          wmax = (float*)(smem + OFF_WMAX);

    // ---- load x slice + bf16 hi/lo split ----
    for (int i = tid; i < 384; i += 256) {
        int t = t0 + i;
        float v = (t < T_LEN) ? x[b * T_LEN + t] : 0.0f;
        xs[i] = v;
        __nv_bfloat16 h = __float2bfloat16(v);
        float hf = __bfloat162float(h);
        __nv_bfloat16 lo = __float2bfloat16(v - hf);
        unsigned short hu, lu;
        memcpy(&hu, &h, 2);
        memcpy(&lu, &lo, 2);
        xh[i] = hu; xl[i] = lu;
    }

    // ---- build B tiles: [f][k] rows, padded stride ----
    {
        uint32_t* bh = (uint32_t*)(smem + OFF_BH);
        uint32_t* bl = (uint32_t*)(smem + OFF_BL);
        #pragma unroll
        for (int idx = tid; idx < NF * 64; idx += 256) {
            int f = idx >> 6, c = idx & 63;
            bh[f * (LDA / 2) + c] = g_sh32[idx];
            bl[f * (LDA / 2) + c] = g_sl32[idx];
        }
    }
    __syncthreads();

    // ---- per-window inverse scale 1/(L*(std+eps)) ----
    {
        int w = tid;
        float s = 0.0f, s2 = 0.0f;
        #pragma unroll 8
        for (int l = 0; l < L_LEN; ++l) {
            float v = xs[w + l];
            s += v;
            s2 = fmaf(v, v, s2);
        }
        float mu  = s * (1.0f / L_LEN);
        float var = fmaxf(s2 * (1.0f / L_LEN) - mu * mu, 0.0f);
        ws[w] = 1.0f / ((sqrtf(var) + EPSF) * (float)L_LEN);
    }

    // ---- build A tiles: row w, col k = x[w+k]; packed u32 col-pairs ----
    {
        uint32_t* ah = (uint32_t*)(smem + OFF_AH);
        uint32_t* al = (uint32_t*)(smem + OFF_AL);
        const int w = tid;
        #pragma unroll 8
        for (int cp = 0; cp < 64; ++cp) {
            int p = w + 2 * cp;
            ah[w * (LDA / 2) + cp] = (uint32_t)xh[p] | ((uint32_t)xh[p + 1] << 16);
            al[w * (LDA / 2) + cp] = (uint32_t)xl[p] | ((uint32_t)xl[p + 1] << 16);
        }
    }
    __syncthreads();

    // ---- mma mainloop ----
    float c[4][8][4];
    #pragma unroll
    for (int mt = 0; mt < 4; ++mt)
        #pragma unroll
        for (int nt = 0; nt < 8; ++nt)
            #pragma unroll
            for (int r = 0; r < 4; ++r) c[mt][nt][r] = 0.0f;

    // per-lane ldmatrix base offsets
    const int quad = lid >> 3, r8 = lid & 7;
    const uint32_t aLane = ((warpRow * 64 + (quad & 1) * 8 + r8) * LDA + (quad >> 1) * 8) * 2;
    const uint32_t bLane = ((warpCol * 64 + (quad >> 1) * 8 + r8) * LDA + (quad & 1) * 8) * 2;

    const uint32_t aTile[3] = {sbase + OFF_AH, sbase + OFF_AL, sbase + OFF_AH};
    const uint32_t bTile[3] = {sbase + OFF_BH, sbase + OFF_BH, sbase + OFF_BL};

    #pragma unroll
    for (int p = 0; p < 3; ++p) {
        const uint32_t aB = aTile[p] + aLane;
        const uint32_t bB = bTile[p] + bLane;
        #pragma unroll
        for (int ks = 0; ks < 8; ++ks) {
            uint32_t a[4][4], bb[4][4];
            #pragma unroll
            for (int mt = 0; mt < 4; ++mt)
                ldsm_x4(a[mt], aB + mt * (16 * LDA * 2) + ks * 32);
            #pragma unroll
            for (int np = 0; np < 4; ++np)
                ldsm_x4(bb[np], bB + np * (16 * LDA * 2) + ks * 32);
            #pragma unroll
            for (int mt = 0; mt < 4; ++mt) {
                #pragma unroll
                for (int np = 0; np < 4; ++np) {
                    mma_bf16(c[mt][2 * np],     a[mt], &bb[np][0]);
                    mma_bf16(c[mt][2 * np + 1], a[mt], &bb[np][2]);
                }
            }
        }
    }

    // ---- epilogue: scale, mask, max over windows ----
    const int g = lid >> 2, tig = lid & 3;
    float sc[4][2];
    int   vld[4][2];
    #pragma unroll
    for (int mt = 0; mt < 4; ++mt)
        #pragma unroll
        for (int h = 0; h < 2; ++h) {
            int row = warpRow * 64 + mt * 16 + g + h * 8;
            sc[mt][h]  = ws[row];
            vld[mt][h] = (t0 + row < NWIN);
        }

    float m[8][2];
    #pragma unroll
    for (int nt = 0; nt < 8; ++nt)
        #pragma unroll
        for (int d = 0; d < 2; ++d) {
            float mm = -INFINITY;
            #pragma unroll
            for (int mt = 0; mt < 4; ++mt)
                #pragma unroll
                for (int h = 0; h < 2; ++h) {
                    float v = c[mt][nt][h * 2 + d] * sc[mt][h];
                    v = vld[mt][h] ? v : -INFINITY;
                    mm = fmaxf(mm, v);
                }
            m[nt][d] = mm;
        }

    // reduce across the 8 row-groups (lanes xor 4,8,16)
    #pragma unroll
    for (int nt = 0; nt < 8; ++nt)
        #pragma unroll
        for (int d = 0; d < 2; ++d) {
            float v = m[nt][d];
            #pragma unroll
            for (int off = 4; off < 32; off <<= 1)
                v = fmaxf(v, __shfl_xor_sync(0xffffffffu, v, off));
            m[nt][d] = v;
        }

    if (g == 0) {
        #pragma unroll
        for (int nt = 0; nt < 8; ++nt)
            #pragma unroll
            for (int d = 0; d < 2; ++d)
                wmax[warpRow * NF + warpCol * 64 + nt * 8 + tig * 2 + d] = m[nt][d];
    }
    __syncthreads();

    if (tid < NF) {
        float mm = fmaxf(fmaxf(wmax[tid], wmax[NF + tid]),
                         fmaxf(wmax[2 * NF + tid], wmax[3 * NF + tid]));
        g_scratch[(b * NTILE + tp) * NF + tid] = mm;
    }
}

// ============================================================
// Kernel 3: final max over tiles
// ============================================================
__global__ void reduce_max_kernel(float* __restrict__ out) {
    const int b = blockIdx.x;
    const int f = threadIdx.x;
    float m = -INFINITY;
    #pragma unroll
    for (int t = 0; t < NTILE; ++t)
        m = fmaxf(m, g_scratch[(b * NTILE + t) * NF + f]);
    out[b * NF + f] = m;
}

extern "C" void kernel_launch(void* const* d_in, const int* in_sizes, int n_in,
                              void* d_out, int out_size) {
    const float* x  = (const float*)d_in[0];   // (256, 4096) fp32
    const float* sh = (const float*)d_in[1];   // (8, 16, 128) fp32
    float* out = (float*)d_out;                // (256, 128) fp32

    cudaFuncSetAttribute(shapelet_mma_kernel,
                         cudaFuncAttributeMaxDynamicSharedMemorySize, SMEM_DYN);

    prep_snorm_kernel<<<NF, L_LEN>>>(sh);
    dim3 grid(NTILE, B_SZ);
    shapelet_mma_kernel<<<grid, 256, SMEM_DYN>>>(x);
    reduce_max_kernel<<<B_SZ, NF>>>(out);
}

// round 6
// speedup vs baseline: 4.0816x; 1.6454x over previous
#include <cuda_runtime.h>
#include <cuda_fp16.h>
#include <math.h>
#include <stdint.h>
#include <string.h>

#define T_LEN   4096
#define L_LEN   128
#define NF      128
#define NWIN    3969
#define B_SZ    256
#define TW      128         // windows per CTA
#define NTILE   32          // 32 x 128 = 4096 >= 3969
#define EPSF    1e-6f
#define LDA     136         // padded row stride (halfs): 272B, conflict-free LDSM

// ---------------- device scratch ----------------
__device__ float    g_scratch[B_SZ * NTILE * NF];
__device__ uint32_t g_s16[NF * 64];     // s_norm fp16x2, [f][k/2]

// ---------------- smem layout (bytes) ----------------
#define OFF_A     0          // 128 x 136 half = 34816
#define OFF_B     34816      // 128 x 136 half = 34816
#define OFF_XS    69632      // float[384]  = 1536
#define OFF_XH    71168      // ushort[384] = 768 (+pad)
#define OFF_WS    71936      // float[128]  = 512
#define OFF_WMAX  72448      // float[4][128] = 2048
#define SMEM_DYN  74496

__device__ __forceinline__ uint32_t smem_to_u32(const void* p) {
    uint32_t a;
    asm("{ .reg .u64 t; cvta.to.shared.u64 t, %1; cvt.u32.u64 %0, t; }" : "=r"(a) : "l"(p));
    return a;
}
__device__ __forceinline__ void ldsm_x4(uint32_t* r, uint32_t addr) {
    asm volatile("ldmatrix.sync.aligned.m8n8.x4.shared.b16 {%0,%1,%2,%3}, [%4];"
                 : "=r"(r[0]), "=r"(r[1]), "=r"(r[2]), "=r"(r[3]) : "r"(addr));
}
__device__ __forceinline__ void mma_fp16(float* c, const uint32_t* a, const uint32_t* b) {
    asm volatile(
        "mma.sync.aligned.m16n8k16.row.col.f32.f16.f16.f32 "
        "{%0,%1,%2,%3}, {%4,%5,%6,%7}, {%8,%9}, {%0,%1,%2,%3};"
        : "+f"(c[0]), "+f"(c[1]), "+f"(c[2]), "+f"(c[3])
        : "r"(a[0]), "r"(a[1]), "r"(a[2]), "r"(a[3]), "r"(b[0]), "r"(b[1]));
}

// ============================================================
// Kernel 1: z-normalize shapelets -> fp16 packed
// ============================================================
__global__ void prep_snorm_kernel(const float* __restrict__ sh) {
    const int f = blockIdx.x;
    const int l = threadIdx.x;
    __shared__ float red[128];
    __shared__ unsigned short th[128];

    float v = sh[f * L_LEN + l];
    red[l] = v;
    __syncthreads();
    #pragma unroll
    for (int s = 64; s > 0; s >>= 1) { if (l < s) red[l] += red[l + s]; __syncthreads(); }
    float mu = red[0] * (1.0f / L_LEN);
    __syncthreads();
    float d = v - mu;
    red[l] = d * d;
    __syncthreads();
    #pragma unroll
    for (int s = 64; s > 0; s >>= 1) { if (l < s) red[l] += red[l + s]; __syncthreads(); }
    float stdv = sqrtf(red[0] * (1.0f / L_LEN)) + EPSF;
    float sn = d / stdv;

    __half h = __float2half(sn);
    unsigned short hu;
    memcpy(&hu, &h, 2);
    th[l] = hu;
    __syncthreads();
    if (l < 64)
        g_s16[f * 64 + l] = (uint32_t)th[2 * l] | ((uint32_t)th[2 * l + 1] << 16);
}

// ============================================================
// Kernel 2: fp16 single-pass mma.sync. CTA = (tile, batch): 128 win x 128 filt.
// 8 warps (4 M-rows x 2 N-cols), warp tile 32x64. 2 CTAs/SM.
// ============================================================
__global__ __launch_bounds__(256, 2)
void shapelet_mma_kernel(const float* __restrict__ x) {
    extern __shared__ char smem[];
    const uint32_t sbase = smem_to_u32(smem);

    const int tp  = blockIdx.x;        // 0..31
    const int b   = blockIdx.y;        // 0..255
    const int tid = threadIdx.x;
    const int wid = tid >> 5;
    const int lid = tid & 31;
    const int warpRow = wid >> 1;      // 0..3 (M, 32 rows each)
    const int warpCol = wid & 1;       // 0..1 (N, 64 cols each)
    const int t0  = tp * TW;

    float*          xs = (float*)(smem + OFF_XS);
    unsigned short* xh = (unsigned short*)(smem + OFF_XH);
    float*          ws = (float*)(smem + OFF_WS);
    float*          wmax = (float*)(smem + OFF_WMAX);

    // ---- load x slice (need 255, pad to 384) + fp16 convert ----
    for (int i = tid; i < 384; i += 256) {
        int t = t0 + i;
        float v = (t < T_LEN) ? x[b * T_LEN + t] : 0.0f;
        xs[i] = v;
        __half h = __float2half(v);
        unsigned short hu;
        memcpy(&hu, &h, 2);
        xh[i] = hu;
    }

    // ---- build B tile: [f][k], padded stride ----
    {
        uint32_t* bt = (uint32_t*)(smem + OFF_B);
        #pragma unroll
        for (int idx = tid; idx < NF * 64; idx += 256) {
            int f = idx >> 6, c = idx & 63;
            bt[f * (LDA / 2) + c] = g_s16[idx];
        }
    }
    __syncthreads();

    // ---- per-window inverse scale 1/(L*(std+eps)) ----
    if (tid < TW) {
        int w = tid;
        float s = 0.0f, s2 = 0.0f;
        #pragma unroll 8
        for (int l = 0; l < L_LEN; ++l) {
            float v = xs[w + l];
            s += v;
            s2 = fmaf(v, v, s2);
        }
        float mu  = s * (1.0f / L_LEN);
        float var = fmaxf(s2 * (1.0f / L_LEN) - mu * mu, 0.0f);
        ws[w] = 1.0f / ((sqrtf(var) + EPSF) * (float)L_LEN);
    }

    // ---- build A tile: A[w][k] = xh[w+k] ----
    {
        uint32_t* at = (uint32_t*)(smem + OFF_A);
        #pragma unroll
        for (int idx = tid; idx < TW * 64; idx += 256) {
            int w = idx >> 6, cp = idx & 63;
            int p = w + 2 * cp;
            at[w * (LDA / 2) + cp] = (uint32_t)xh[p] | ((uint32_t)xh[p + 1] << 16);
        }
    }
    __syncthreads();

    // ---- mma mainloop: warp 32x64, K=128 in 8 k16 steps ----
    float c[2][8][4];
    #pragma unroll
    for (int mt = 0; mt < 2; ++mt)
        #pragma unroll
        for (int nt = 0; nt < 8; ++nt)
            #pragma unroll
            for (int r = 0; r < 4; ++r) c[mt][nt][r] = 0.0f;

    const int quad = lid >> 3, r8 = lid & 7;
    const uint32_t aB = sbase + OFF_A +
        ((warpRow * 32 + (quad & 1) * 8 + r8) * LDA + (quad >> 1) * 8) * 2;
    const uint32_t bB = sbase + OFF_B +
        ((warpCol * 64 + (quad >> 1) * 8 + r8) * LDA + (quad & 1) * 8) * 2;

    #pragma unroll
    for (int ks = 0; ks < 8; ++ks) {
        uint32_t a[2][4], bb[4][4];
        #pragma unroll
        for (int mt = 0; mt < 2; ++mt)
            ldsm_x4(a[mt], aB + mt * (16 * LDA * 2) + ks * 32);
        #pragma unroll
        for (int np = 0; np < 4; ++np)
            ldsm_x4(bb[np], bB + np * (16 * LDA * 2) + ks * 32);
        #pragma unroll
        for (int mt = 0; mt < 2; ++mt) {
            #pragma unroll
            for (int np = 0; np < 4; ++np) {
                mma_fp16(c[mt][2 * np],     a[mt], &bb[np][0]);
                mma_fp16(c[mt][2 * np + 1], a[mt], &bb[np][2]);
            }
        }
    }

    // ---- epilogue: scale, mask, max over windows ----
    const int g = lid >> 2, tig = lid & 3;
    float sc[2][2];
    int   vld[2][2];
    #pragma unroll
    for (int mt = 0; mt < 2; ++mt)
        #pragma unroll
        for (int h = 0; h < 2; ++h) {
            int row = warpRow * 32 + mt * 16 + g + h * 8;
            sc[mt][h]  = ws[row];
            vld[mt][h] = (t0 + row < NWIN);
        }

    float m[8][2];
    #pragma unroll
    for (int nt = 0; nt < 8; ++nt)
        #pragma unroll
        for (int d = 0; d < 2; ++d) {
            float mm = -INFINITY;
            #pragma unroll
            for (int mt = 0; mt < 2; ++mt)
                #pragma unroll
                for (int h = 0; h < 2; ++h) {
                    float v = c[mt][nt][h * 2 + d] * sc[mt][h];
                    v = vld[mt][h] ? v : -INFINITY;
                    mm = fmaxf(mm, v);
                }
            m[nt][d] = mm;
        }

    #pragma unroll
    for (int nt = 0; nt < 8; ++nt)
        #pragma unroll
        for (int d = 0; d < 2; ++d) {
            float v = m[nt][d];
            #pragma unroll
            for (int off = 4; off < 32; off <<= 1)
                v = fmaxf(v, __shfl_xor_sync(0xffffffffu, v, off));
            m[nt][d] = v;
        }

    if (g == 0) {
        #pragma unroll
        for (int nt = 0; nt < 8; ++nt)
            #pragma unroll
            for (int d = 0; d < 2; ++d)
                wmax[warpRow * NF + warpCol * 64 + nt * 8 + tig * 2 + d] = m[nt][d];
    }
    __syncthreads();

    if (tid < NF) {
        float mm = fmaxf(fmaxf(wmax[tid], wmax[NF + tid]),
                         fmaxf(wmax[2 * NF + tid], wmax[3 * NF + tid]));
        g_scratch[(b * NTILE + tp) * NF + tid] = mm;
    }
}

// ============================================================
// Kernel 3: final max over tiles
// ============================================================
__global__ void reduce_max_kernel(float* __restrict__ out) {
    const int b = blockIdx.x;
    const int f = threadIdx.x;
    float m = -INFINITY;
    #pragma unroll
    for (int t = 0; t < NTILE; ++t)
        m = fmaxf(m, g_scratch[(b * NTILE + t) * NF + f]);
    out[b * NF + f] = m;
}

extern "C" void kernel_launch(void* const* d_in, const int* in_sizes, int n_in,
                              void* d_out, int out_size) {
    const float* x  = (const float*)d_in[0];   // (256, 4096) fp32
    const float* sh = (const float*)d_in[1];   // (8, 16, 128) fp32
    float* out = (float*)d_out;                // (256, 128) fp32

    cudaFuncSetAttribute(shapelet_mma_kernel,
                         cudaFuncAttributeMaxDynamicSharedMemorySize, SMEM_DYN);

    prep_snorm_kernel<<<NF, L_LEN>>>(sh);
    dim3 grid(NTILE, B_SZ);
    shapelet_mma_kernel<<<grid, 256, SMEM_DYN>>>(x);
    reduce_max_kernel<<<B_SZ, NF>>>(out);
}

// round 7
// speedup vs baseline: 7.5934x; 1.8604x over previous
#include <cuda_runtime.h>
#include <cuda_fp16.h>
#include <math.h>
#include <stdint.h>
#include <string.h>

#define T_LEN   4096
#define TPAD    4480        // padded x16 row (halfs)
#define L_LEN   128
#define NF      128
#define NWIN    3969
#define B_SZ    256
#define TW      128         // windows per tile
#define NTILE   32
#define NTG     8           // tile-groups per batch
#define TPC     4           // tiles per CTA
#define EPSF    1e-6f
#define LDA     136         // padded A/B row stride (halfs)

// ---------------- device scratch ----------------
__device__ float    g_scratch[B_SZ * NTG * NF];
__device__ uint32_t g_s16[NF * 64];          // s_norm fp16x2 [f][k/2]
__device__ __half   g_x16[B_SZ * TPAD];      // x in fp16, padded rows
__device__ float    g_ws[B_SZ * T_LEN];      // per-window inv scale

// ---------------- smem layout (main kernel, bytes) ----------------
#define OFF_A     0          // 128 x 136 half = 34816
#define OFF_B     34816      // 128 x 136 half = 34816
#define OFF_X16   69632      // u32[192] = 768 (+pad to 1024)
#define OFF_WS    70656      // float[128] = 512
#define OFF_WMAX  71168      // float[4][128] = 2048
#define SMEM_DYN  73216

__device__ __forceinline__ uint32_t smem_to_u32(const void* p) {
    uint32_t a;
    asm("{ .reg .u64 t; cvta.to.shared.u64 t, %1; cvt.u32.u64 %0, t; }" : "=r"(a) : "l"(p));
    return a;
}
__device__ __forceinline__ void ldsm_x4(uint32_t* r, uint32_t addr) {
    asm volatile("ldmatrix.sync.aligned.m8n8.x4.shared.b16 {%0,%1,%2,%3}, [%4];"
                 : "=r"(r[0]), "=r"(r[1]), "=r"(r[2]), "=r"(r[3]) : "r"(addr));
}
__device__ __forceinline__ void mma_fp16(float* c, const uint32_t* a, const uint32_t* b) {
    asm volatile(
        "mma.sync.aligned.m16n8k16.row.col.f32.f16.f16.f32 "
        "{%0,%1,%2,%3}, {%4,%5,%6,%7}, {%8,%9}, {%0,%1,%2,%3};"
        : "+f"(c[0]), "+f"(c[1]), "+f"(c[2]), "+f"(c[3])
        : "r"(a[0]), "r"(a[1]), "r"(a[2]), "r"(a[3]), "r"(b[0]), "r"(b[1]));
}

// ============================================================
// Kernel 1: z-normalize shapelets -> fp16 packed
// ============================================================
__global__ void prep_snorm_kernel(const float* __restrict__ sh) {
    const int f = blockIdx.x;
    const int l = threadIdx.x;
    __shared__ float red[128];
    __shared__ unsigned short th[128];

    float v = sh[f * L_LEN + l];
    red[l] = v;
    __syncthreads();
    #pragma unroll
    for (int s = 64; s > 0; s >>= 1) { if (l < s) red[l] += red[l + s]; __syncthreads(); }
    float mu = red[0] * (1.0f / L_LEN);
    __syncthreads();
    float d = v - mu;
    red[l] = d * d;
    __syncthreads();
    #pragma unroll
    for (int s = 64; s > 0; s >>= 1) { if (l < s) red[l] += red[l + s]; __syncthreads(); }
    float stdv = sqrtf(red[0] * (1.0f / L_LEN)) + EPSF;
    float sn = d / stdv;

    __half h = __float2half(sn);
    unsigned short hu;
    memcpy(&hu, &h, 2);
    th[l] = hu;
    __syncthreads();
    if (l < 64)
        g_s16[f * 64 + l] = (uint32_t)th[2 * l] | ((uint32_t)th[2 * l + 1] << 16);
}

// ============================================================
// Kernel 2: per-batch prep. fp16 convert + prefix-sum window scales.
// One block per batch, 256 threads, 16 elements each.
// ============================================================
__global__ __launch_bounds__(256)
void prep_x_kernel(const float* __restrict__ x) {
    const int b   = blockIdx.x;
    const int tid = threadIdx.x;
    __shared__ float P[T_LEN + 1];    // exclusive prefix of x
    __shared__ float P2[T_LEN + 1];   // exclusive prefix of x^2
    __shared__ float cs[256], cs2[256];

    const int base = tid * 16;
    float lx[16];
    float s = 0.0f, s2 = 0.0f;
    #pragma unroll
    for (int j = 0; j < 16; j += 2) {
        float v0 = x[b * T_LEN + base + j];
        float v1 = x[b * T_LEN + base + j + 1];
        lx[j] = v0; lx[j + 1] = v1;
        s += v0 + v1;
        s2 = fmaf(v0, v0, s2);
        s2 = fmaf(v1, v1, s2);
        __half2 h2 = __floats2half2_rn(v0, v1);
        *(__half2*)&g_x16[b * TPAD + base + j] = h2;
    }
    // zero-pad tail [4096, 4480)
    if (tid < (TPAD - T_LEN) / 2)
        *(__half2*)&g_x16[b * TPAD + T_LEN + tid * 2] = __floats2half2_rn(0.f, 0.f);

    cs[tid] = s; cs2[tid] = s2;
    __syncthreads();
    // Hillis-Steele inclusive scan over 256 chunk sums
    #pragma unroll
    for (int off = 1; off < 256; off <<= 1) {
        float a  = (tid >= off) ? cs[tid - off]  : 0.0f;
        float a2 = (tid >= off) ? cs2[tid - off] : 0.0f;
        __syncthreads();
        cs[tid] += a; cs2[tid] += a2;
        __syncthreads();
    }
    float r  = (tid == 0) ? 0.0f : cs[tid - 1];
    float r2 = (tid == 0) ? 0.0f : cs2[tid - 1];
    if (tid == 0) { P[0] = 0.0f; P2[0] = 0.0f; }
    #pragma unroll
    for (int j = 0; j < 16; ++j) {
        r  += lx[j];
        r2  = fmaf(lx[j], lx[j], r2);
        P[base + j + 1]  = r;
        P2[base + j + 1] = r2;
    }
    __syncthreads();
    #pragma unroll
    for (int j = 0; j < 16; ++j) {
        int w = base + j;
        float wsv = 0.0f;
        if (w < NWIN) {
            float su = P[w + L_LEN] - P[w];
            float qu = P2[w + L_LEN] - P2[w];
            float mu = su * (1.0f / L_LEN);
            float var = fmaxf(qu * (1.0f / L_LEN) - mu * mu, 0.0f);
            wsv = 1.0f / ((sqrtf(var) + EPSF) * (float)L_LEN);
        }
        g_ws[b * T_LEN + w] = wsv;
    }
}

// ============================================================
// Kernel 3: main mma kernel. CTA = (tile-group, batch): 4 tiles of
// 128 win x 128 filt. B loaded once; running max in regs across tiles.
// ============================================================
__global__ __launch_bounds__(256, 2)
void shapelet_mma_kernel() {
    extern __shared__ char smem[];
    const uint32_t sbase = smem_to_u32(smem);

    const int tg  = blockIdx.x;        // 0..7
    const int b   = blockIdx.y;        // 0..255
    const int tid = threadIdx.x;
    const int lid = tid & 31;
    const int wid = tid >> 5;
    const int warpRow = wid >> 1;      // 0..3 (M)
    const int warpCol = wid & 1;       // 0..1 (N)

    uint32_t* x16s = (uint32_t*)(smem + OFF_X16);
    float*    ws   = (float*)(smem + OFF_WS);
    float*    wmax = (float*)(smem + OFF_WMAX);

    const uint32_t* g_x16u = (const uint32_t*)g_x16;
    const int xrow = b * (TPAD / 2);

    // ---- load B tile once ----
    {
        uint32_t* bt = (uint32_t*)(smem + OFF_B);
        #pragma unroll
        for (int idx = tid; idx < NF * 64; idx += 256) {
            int f = idx >> 6, c = idx & 63;
            bt[f * (LDA / 2) + c] = g_s16[idx];
        }
    }
    // ---- load first tile's x16 + ws ----
    {
        int t0 = tg * TPC * TW;
        if (tid < 192) x16s[tid] = g_x16u[xrow + t0 / 2 + tid];
        if (tid < 128) ws[tid] = g_ws[b * T_LEN + t0 + tid];
    }
    __syncthreads();

    const int quad = lid >> 3, r8 = lid & 7;
    const uint32_t aB = sbase + OFF_A +
        ((warpRow * 32 + (quad & 1) * 8 + r8) * LDA + (quad >> 1) * 8) * 2;
    const uint32_t bB = sbase + OFF_B +
        ((warpCol * 64 + (quad >> 1) * 8 + r8) * LDA + (quad & 1) * 8) * 2;
    const int g = lid >> 2, tig = lid & 3;

    float m[8][2];
    #pragma unroll
    for (int nt = 0; nt < 8; ++nt) { m[nt][0] = -INFINITY; m[nt][1] = -INFINITY; }

    for (int it = 0; it < TPC; ++it) {
        const int t0 = (tg * TPC + it) * TW;

        // ---- build A from x16 slice: A[w][k] = x16[w+k] (funnel shift for odd w) ----
        {
            uint32_t* at = (uint32_t*)(smem + OFF_A);
            #pragma unroll
            for (int idx = tid; idx < TW * 64; idx += 256) {
                int w = idx >> 6, cp = idx & 63;
                uint32_t v;
                if (w & 1) {
                    uint32_t lo = x16s[(w >> 1) + cp];
                    uint32_t hi = x16s[(w >> 1) + cp + 1];
                    v = __funnelshift_r(lo, hi, 16);
                } else {
                    v = x16s[(w >> 1) + cp];
                }
                at[w * (LDA / 2) + cp] = v;
            }
        }
        __syncthreads();

        // ---- prefetch next tile's x16 + ws into regs ----
        uint32_t pf_x = 0; float pf_w = 0.0f;
        if (it + 1 < TPC) {
            int tn = t0 + TW;
            if (tid < 192) pf_x = g_x16u[xrow + tn / 2 + tid];
            if (tid < 128) pf_w = g_ws[b * T_LEN + tn + tid];
        }

        // ---- mma: warp 32x64, K=128 ----
        float c[2][8][4];
        #pragma unroll
        for (int mt = 0; mt < 2; ++mt)
            #pragma unroll
            for (int nt = 0; nt < 8; ++nt)
                #pragma unroll
                for (int r = 0; r < 4; ++r) c[mt][nt][r] = 0.0f;

        #pragma unroll
        for (int ks = 0; ks < 8; ++ks) {
            uint32_t a[2][4], bb[4][4];
            #pragma unroll
            for (int mt = 0; mt < 2; ++mt)
                ldsm_x4(a[mt], aB + mt * (16 * LDA * 2) + ks * 32);
            #pragma unroll
            for (int np = 0; np < 4; ++np)
                ldsm_x4(bb[np], bB + np * (16 * LDA * 2) + ks * 32);
            #pragma unroll
            for (int mt = 0; mt < 2; ++mt)
                #pragma unroll
                for (int np = 0; np < 4; ++np) {
                    mma_fp16(c[mt][2 * np],     a[mt], &bb[np][0]);
                    mma_fp16(c[mt][2 * np + 1], a[mt], &bb[np][2]);
                }
        }

        // ---- fold: scale, mask, running max ----
        #pragma unroll
        for (int mt = 0; mt < 2; ++mt)
            #pragma unroll
            for (int h = 0; h < 2; ++h) {
                int row = warpRow * 32 + mt * 16 + g + h * 8;
                float sc = ws[row];
                bool vld = (t0 + row < NWIN);
                #pragma unroll
                for (int nt = 0; nt < 8; ++nt)
                    #pragma unroll
                    for (int d = 0; d < 2; ++d) {
                        float v = c[mt][nt][h * 2 + d] * sc;
                        if (vld) m[nt][d] = fmaxf(m[nt][d], v);
                    }
            }

        __syncthreads();   // done with x16s/ws/A
        if (it + 1 < TPC) {
            if (tid < 192) x16s[tid] = pf_x;
            if (tid < 128) ws[tid] = pf_w;
            __syncthreads();
        }
    }

    // ---- final reduce: shfl across row-groups, then across warps ----
    #pragma unroll
    for (int nt = 0; nt < 8; ++nt)
        #pragma unroll
        for (int d = 0; d < 2; ++d) {
            float v = m[nt][d];
            #pragma unroll
            for (int off = 4; off < 32; off <<= 1)
                v = fmaxf(v, __shfl_xor_sync(0xffffffffu, v, off));
            m[nt][d] = v;
        }
    if (g == 0) {
        #pragma unroll
        for (int nt = 0; nt < 8; ++nt)
            #pragma unroll
            for (int d = 0; d < 2; ++d)
                wmax[warpRow * NF + warpCol * 64 + nt * 8 + tig * 2 + d] = m[nt][d];
    }
    __syncthreads();
    if (tid < NF) {
        float mm = fmaxf(fmaxf(wmax[tid], wmax[NF + tid]),
                         fmaxf(wmax[2 * NF + tid], wmax[3 * NF + tid]));
        g_scratch[(b * NTG + tg) * NF + tid] = mm;
    }
}

// ============================================================
// Kernel 4: final max over tile-groups
// ============================================================
__global__ void reduce_max_kernel(float* __restrict__ out) {
    const int b = blockIdx.x;
    const int f = threadIdx.x;
    float m = -INFINITY;
    #pragma unroll
    for (int t = 0; t < NTG; ++t)
        m = fmaxf(m, g_scratch[(b * NTG + t) * NF + f]);
    out[b * NF + f] = m;
}

extern "C" void kernel_launch(void* const* d_in, const int* in_sizes, int n_in,
                              void* d_out, int out_size) {
    const float* x  = (const float*)d_in[0];   // (256, 4096) fp32
    const float* sh = (const float*)d_in[1];   // (8, 16, 128) fp32
    float* out = (float*)d_out;                // (256, 128) fp32

    cudaFuncSetAttribute(shapelet_mma_kernel,
                         cudaFuncAttributeMaxDynamicSharedMemorySize, SMEM_DYN);

    prep_snorm_kernel<<<NF, L_LEN>>>(sh);
    prep_x_kernel<<<B_SZ, 256>>>(x);
    dim3 grid(NTG, B_SZ);
    shapelet_mma_kernel<<<grid, 256, SMEM_DYN>>>();
    reduce_max_kernel<<<B_SZ, NF>>>(out);
}

// round 8
// speedup vs baseline: 9.4472x; 1.2441x over previous
#include <cuda_runtime.h>
#include <cuda_fp16.h>
#include <math.h>
#include <stdint.h>
#include <string.h>

#define T_LEN   4096
#define TPAD    4480        // padded x16 row (halfs)
#define L_LEN   128
#define NF      128
#define NWIN    3969
#define B_SZ    256
#define TW      128         // windows per tile
#define NTG     8           // tile-groups per batch (512 windows each)
#define TPC     4           // tiles per CTA
#define EPSF    1e-6f
#define LDA     136         // padded B row stride (halfs) -> 272B

// ---------------- device scratch ----------------
__device__ float    g_scratch[B_SZ * NTG * NF];
__device__ uint32_t g_s16[NF * 64];          // s_norm fp16x2 [f][k/2]
__device__ __half   g_x16[B_SZ * TPAD];      // x in fp16, padded rows
__device__ float    g_ws[B_SZ * T_LEN];      // per-window inv scale

// ---------------- smem layout (main kernel, bytes) ----------------
#define OFF_B     0          // 128 x 136 half = 34816
#define OFF_XC    34816      // 8 copies x 1296 B = 10368 (stride%128==16 -> conflict-free)
#define OFF_WS    45184      // float[512] = 2048
#define OFF_WMAX  47232      // float[2][128] = 1024
#define SMEM_DYN  48256

__device__ __forceinline__ uint32_t smem_to_u32(const void* p) {
    uint32_t a;
    asm("{ .reg .u64 t; cvta.to.shared.u64 t, %1; cvt.u32.u64 %0, t; }" : "=r"(a) : "l"(p));
    return a;
}
__device__ __forceinline__ void ldsm_x4(uint32_t* r, uint32_t addr) {
    asm volatile("ldmatrix.sync.aligned.m8n8.x4.shared.b16 {%0,%1,%2,%3}, [%4];"
                 : "=r"(r[0]), "=r"(r[1]), "=r"(r[2]), "=r"(r[3]) : "r"(addr));
}
__device__ __forceinline__ void mma_fp16(float* c, const uint32_t* a, const uint32_t* b) {
    asm volatile(
        "mma.sync.aligned.m16n8k16.row.col.f32.f16.f16.f32 "
        "{%0,%1,%2,%3}, {%4,%5,%6,%7}, {%8,%9}, {%0,%1,%2,%3};"
        : "+f"(c[0]), "+f"(c[1]), "+f"(c[2]), "+f"(c[3])
        : "r"(a[0]), "r"(a[1]), "r"(a[2]), "r"(a[3]), "r"(b[0]), "r"(b[1]));
}

// ============================================================
// Kernel 1 (merged prep): blocks 0..127 -> shapelet z-norm,
// blocks 128..383 -> per-batch fp16 convert + prefix-sum scales.
// ============================================================
__global__ __launch_bounds__(256)
void prep_all_kernel(const float* __restrict__ x, const float* __restrict__ sh) {
    const int bid = blockIdx.x;
    const int tid = threadIdx.x;

    if (bid < NF) {
        // ---- shapelet z-normalize -> fp16 packed ----
        __shared__ float red[128];
        __shared__ unsigned short th[128];
        const int f = bid, l = tid;
        float v = 0.0f;
        if (l < 128) { v = sh[f * L_LEN + l]; red[l] = v; }
        __syncthreads();
        #pragma unroll
        for (int s = 64; s > 0; s >>= 1) { if (l < s) red[l] += red[l + s]; __syncthreads(); }
        float mu = red[0] * (1.0f / L_LEN);
        __syncthreads();
        float d = v - mu;
        if (l < 128) red[l] = d * d;
        __syncthreads();
        #pragma unroll
        for (int s = 64; s > 0; s >>= 1) { if (l < s) red[l] += red[l + s]; __syncthreads(); }
        float stdv = sqrtf(red[0] * (1.0f / L_LEN)) + EPSF;
        if (l < 128) {
            float sn = d / stdv;
            __half h = __float2half(sn);
            unsigned short hu;
            memcpy(&hu, &h, 2);
            th[l] = hu;
        }
        __syncthreads();
        if (l < 64)
            g_s16[f * 64 + l] = (uint32_t)th[2 * l] | ((uint32_t)th[2 * l + 1] << 16);
    } else {
        // ---- per-batch x prep ----
        const int b = bid - NF;
        __shared__ float P[T_LEN + 1];
        __shared__ float P2[T_LEN + 1];
        __shared__ float cs[256], cs2[256];

        const int base = tid * 16;
        float lx[16];
        float s = 0.0f, s2 = 0.0f;
        #pragma unroll
        for (int j = 0; j < 16; j += 2) {
            float v0 = x[b * T_LEN + base + j];
            float v1 = x[b * T_LEN + base + j + 1];
            lx[j] = v0; lx[j + 1] = v1;
            s += v0 + v1;
            s2 = fmaf(v0, v0, s2);
            s2 = fmaf(v1, v1, s2);
            *(__half2*)&g_x16[b * TPAD + base + j] = __floats2half2_rn(v0, v1);
        }
        if (tid < (TPAD - T_LEN) / 2)
            *(__half2*)&g_x16[b * TPAD + T_LEN + tid * 2] = __floats2half2_rn(0.f, 0.f);

        cs[tid] = s; cs2[tid] = s2;
        __syncthreads();
        #pragma unroll
        for (int off = 1; off < 256; off <<= 1) {
            float a  = (tid >= off) ? cs[tid - off]  : 0.0f;
            float a2 = (tid >= off) ? cs2[tid - off] : 0.0f;
            __syncthreads();
            cs[tid] += a; cs2[tid] += a2;
            __syncthreads();
        }
        float r  = (tid == 0) ? 0.0f : cs[tid - 1];
        float r2 = (tid == 0) ? 0.0f : cs2[tid - 1];
        if (tid == 0) { P[0] = 0.0f; P2[0] = 0.0f; }
        #pragma unroll
        for (int j = 0; j < 16; ++j) {
            r  += lx[j];
            r2  = fmaf(lx[j], lx[j], r2);
            P[base + j + 1]  = r;
            P2[base + j + 1] = r2;
        }
        __syncthreads();
        #pragma unroll
        for (int j = 0; j < 16; ++j) {
            int w = base + j;
            float wsv = 0.0f;
            if (w < NWIN) {
                float su = P[w + L_LEN] - P[w];
                float qu = P2[w + L_LEN] - P2[w];
                float mu = su * (1.0f / L_LEN);
                float var = fmaxf(qu * (1.0f / L_LEN) - mu * mu, 0.0f);
                wsv = 1.0f / ((sqrtf(var) + EPSF) * (float)L_LEN);
            }
            g_ws[b * T_LEN + w] = wsv;
        }
    }
}

// ============================================================
// Kernel 2: main mma kernel. CTA = (tile-group, batch): 512 windows.
// 8 warps = 2 (M=64) x 4 (N=32). A frags via Hankel chain from
// 8 parity-shifted x copies. No A tile, no mainloop syncs.
// ============================================================
__global__ __launch_bounds__(256, 2)
void shapelet_mma_kernel() {
    extern __shared__ char smem[];
    const uint32_t sbase = smem_to_u32(smem);

    const int tg  = blockIdx.x;        // 0..7
    const int b   = blockIdx.y;        // 0..255
    const int tid = threadIdx.x;
    const int lid = tid & 31;
    const int wid = tid >> 5;
    const int warpRow = wid >> 2;      // 0..1 (64 windows)
    const int warpCol = wid & 3;       // 0..3 (32 filters)
    const int t0g = tg * (TPC * TW);   // 0..3584

    float* ws   = (float*)(smem + OFF_WS);
    float* wmax = (float*)(smem + OFF_WMAX);

    // ---- B tile (once) ----
    {
        uint32_t* bt = (uint32_t*)(smem + OFF_B);
        #pragma unroll
        for (int k = 0; k < 32; ++k) {
            int idx = tid + k * 256;
            int f = idx >> 6, cc = idx & 63;
            bt[f * (LDA / 2) + cc] = g_s16[idx];
        }
    }

    // ---- 8 parity-shifted x copies (once, covers all 4 tiles: 640 halfs) ----
    {
        const uint32_t* gx = (const uint32_t*)g_x16;
        const int xrow = b * (TPAD / 2);
        #pragma unroll
        for (int s = 0; s < 8; ++s) {
            uint32_t* dst = (uint32_t*)(smem + OFF_XC + s * 1296);
            if ((s & 1) == 0) {
                int gb = xrow + (t0g + s) / 2;
                dst[tid] = gx[gb + tid];
                if (tid < 64) dst[256 + tid] = gx[gb + 256 + tid];
            } else {
                int gb = xrow + (t0g + s - 1) / 2;
                uint32_t lo = gx[gb + tid], hi = gx[gb + tid + 1];
                dst[tid] = __funnelshift_r(lo, hi, 16);
                if (tid < 64) {
                    uint32_t lo2 = gx[gb + 256 + tid], hi2 = gx[gb + 257 + tid];
                    dst[256 + tid] = __funnelshift_r(lo2, hi2, 16);
                }
            }
        }
    }

    // ---- window scales for the 512-window range ----
    ws[tid]       = g_ws[b * T_LEN + t0g + tid];
    ws[256 + tid] = g_ws[b * T_LEN + t0g + 256 + tid];
    __syncthreads();

    // ---- lane bases ----
    const int quad = lid >> 3, r8 = lid & 7;
    const int w0 = warpRow * 64 + (quad & 1) * 8 + r8;       // w0 & 7 == r8
    const uint32_t aBase = sbase + OFF_XC + r8 * 1296 + (w0 - r8) * 2 + (quad >> 1) * 16;
    const uint32_t bB = sbase + OFF_B +
        ((warpCol * 32 + (quad >> 1) * 8 + r8) * LDA + (quad & 1) * 8) * 2;
    const int g = lid >> 2, tig = lid & 3;

    float m[4][2];
    #pragma unroll
    for (int nt = 0; nt < 4; ++nt) { m[nt][0] = -INFINITY; m[nt][1] = -INFINITY; }

    for (int it = 0; it < TPC; ++it) {
        const uint32_t aB = aBase + it * 256;     // +128 windows = +256 B

        float c[4][4][4];
        #pragma unroll
        for (int mt = 0; mt < 4; ++mt)
            #pragma unroll
            for (int nt = 0; nt < 4; ++nt)
                #pragma unroll
                for (int r = 0; r < 4; ++r) c[mt][nt][r] = 0.0f;

        // Hankel ring: fr[j mod 4] = A-frag(window-block 0, k-block j)
        uint32_t fr[4][4];
        ldsm_x4(fr[0], aB);
        ldsm_x4(fr[1], aB + 32);
        ldsm_x4(fr[2], aB + 64);

        #pragma unroll
        for (int ks = 0; ks < 8; ++ks) {
            ldsm_x4(fr[(ks + 3) & 3], aB + (ks + 3) * 32);
            uint32_t bb[2][4];
            ldsm_x4(bb[0], bB + ks * 32);
            ldsm_x4(bb[1], bB + 16 * LDA * 2 + ks * 32);
            #pragma unroll
            for (int mt = 0; mt < 4; ++mt) {
                const uint32_t* a = fr[(ks + mt) & 3];   // A(mt*16, ks*16) == A(0,(ks+mt)*16)
                mma_fp16(c[mt][0], a, &bb[0][0]);
                mma_fp16(c[mt][1], a, &bb[0][2]);
                mma_fp16(c[mt][2], a, &bb[1][0]);
                mma_fp16(c[mt][3], a, &bb[1][2]);
            }
        }

        // ---- fold: scale, mask, running max ----
        #pragma unroll
        for (int mt = 0; mt < 4; ++mt)
            #pragma unroll
            for (int h = 0; h < 2; ++h) {
                int row = warpRow * 64 + mt * 16 + g + h * 8;
                float sc = ws[it * 128 + row];
                bool vld = (t0g + it * 128 + row < NWIN);
                #pragma unroll
                for (int nt = 0; nt < 4; ++nt)
                    #pragma unroll
                    for (int d = 0; d < 2; ++d) {
                        float v = c[mt][nt][h * 2 + d] * sc;
                        if (vld) m[nt][d] = fmaxf(m[nt][d], v);
                    }
            }
    }

    // ---- reduce: shfl across row-groups, smem across warpRows ----
    #pragma unroll
    for (int nt = 0; nt < 4; ++nt)
        #pragma unroll
        for (int d = 0; d < 2; ++d) {
            float v = m[nt][d];
            #pragma unroll
            for (int off = 4; off < 32; off <<= 1)
                v = fmaxf(v, __shfl_xor_sync(0xffffffffu, v, off));
            m[nt][d] = v;
        }
    if (g == 0) {
        #pragma unroll
        for (int nt = 0; nt < 4; ++nt)
            #pragma unroll
            for (int d = 0; d < 2; ++d)
                wmax[warpRow * NF + warpCol * 32 + nt * 8 + tig * 2 + d] = m[nt][d];
    }
    __syncthreads();
    if (tid < NF) {
        float mm = fmaxf(wmax[tid], wmax[NF + tid]);
        g_scratch[(b * NTG + tg) * NF + tid] = mm;
    }
}

// ============================================================
// Kernel 3: final max over tile-groups
// ============================================================
__global__ void reduce_max_kernel(float* __restrict__ out) {
    const int b = blockIdx.x;
    const int f = threadIdx.x;
    float m = -INFINITY;
    #pragma unroll
    for (int t = 0; t < NTG; ++t)
        m = fmaxf(m, g_scratch[(b * NTG + t) * NF + f]);
    out[b * NF + f] = m;
}

extern "C" void kernel_launch(void* const* d_in, const int* in_sizes, int n_in,
                              void* d_out, int out_size) {
    const float* x  = (const float*)d_in[0];   // (256, 4096) fp32
    const float* sh = (const float*)d_in[1];   // (8, 16, 128) fp32
    float* out = (float*)d_out;                // (256, 128) fp32

    cudaFuncSetAttribute(shapelet_mma_kernel,
                         cudaFuncAttributeMaxDynamicSharedMemorySize, SMEM_DYN);

    prep_all_kernel<<<NF + B_SZ, 256>>>(x, sh);
    dim3 grid(NTG, B_SZ);
    shapelet_mma_kernel<<<grid, 256, SMEM_DYN>>>();
    reduce_max_kernel<<<B_SZ, NF>>>(out);
}

// round 9
// speedup vs baseline: 9.9895x; 1.0574x over previous
#include <cuda_runtime.h>
#include <cuda_fp16.h>
#include <math.h>
#include <stdint.h>
#include <string.h>

#define T_LEN   4096
#define TPAD    4480        // padded x16 row (halfs)
#define L_LEN   128
#define NF      128
#define NWIN    3969
#define B_SZ    256
#define TW      128         // windows per tile
#define NTG     8           // tile-groups per batch (512 windows each)
#define TPC     4           // tiles per CTA
#define EPSF    1e-6f
#define LDA     136         // padded B row stride (halfs) -> 272B

// ---------------- device scratch ----------------
__device__ float    g_scratch[B_SZ * NTG * NF];
__device__ uint32_t g_s16[NF * 64];          // s_norm fp16x2 [f][k/2]
__device__ __half   g_x16[B_SZ * TPAD];      // x in fp16, padded rows
__device__ float    g_ws[B_SZ * T_LEN];      // per-window inv scale (NaN past NWIN)

// ---------------- smem layout (main kernel, bytes) ----------------
#define OFF_B     0          // 128 x 136 half = 34816
#define OFF_XC    34816      // 8 copies x 1296 B = 10368 (stride%128==16 -> conflict-free)
#define OFF_WS    45184      // float[512] = 2048
#define OFF_WMAX  47232      // float[2][128] = 1024
#define SMEM_DYN  48256

__device__ __forceinline__ uint32_t smem_to_u32(const void* p) {
    uint32_t a;
    asm("{ .reg .u64 t; cvta.to.shared.u64 t, %1; cvt.u32.u64 %0, t; }" : "=r"(a) : "l"(p));
    return a;
}
__device__ __forceinline__ void ldsm_x4(uint32_t* r, uint32_t addr) {
    asm volatile("ldmatrix.sync.aligned.m8n8.x4.shared.b16 {%0,%1,%2,%3}, [%4];"
                 : "=r"(r[0]), "=r"(r[1]), "=r"(r[2]), "=r"(r[3]) : "r"(addr));
}
__device__ __forceinline__ void mma_fp16(float* c, const uint32_t* a, const uint32_t* b) {
    asm volatile(
        "mma.sync.aligned.m16n8k16.row.col.f32.f16.f16.f32 "
        "{%0,%1,%2,%3}, {%4,%5,%6,%7}, {%8,%9}, {%0,%1,%2,%3};"
        : "+f"(c[0]), "+f"(c[1]), "+f"(c[2]), "+f"(c[3])
        : "r"(a[0]), "r"(a[1]), "r"(a[2]), "r"(a[3]), "r"(b[0]), "r"(b[1]));
}

// ============================================================
// Kernel 1 (merged prep): blocks 0..127 -> shapelet z-norm,
// blocks 128..383 -> per-batch fp16 convert + warp-scan window scales.
// ============================================================
__global__ __launch_bounds__(256)
void prep_all_kernel(const float* __restrict__ x, const float* __restrict__ sh) {
    const int bid = blockIdx.x;
    const int tid = threadIdx.x;

    if (bid < NF) {
        // ---- shapelet z-normalize -> fp16 packed ----
        __shared__ float red[128];
        __shared__ unsigned short th[128];
        const int f = bid, l = tid;
        float v = 0.0f;
        if (l < 128) { v = sh[f * L_LEN + l]; red[l] = v; }
        __syncthreads();
        #pragma unroll
        for (int s = 64; s > 0; s >>= 1) { if (l < s) red[l] += red[l + s]; __syncthreads(); }
        float mu = red[0] * (1.0f / L_LEN);
        __syncthreads();
        float d = v - mu;
        if (l < 128) red[l] = d * d;
        __syncthreads();
        #pragma unroll
        for (int s = 64; s > 0; s >>= 1) { if (l < s) red[l] += red[l + s]; __syncthreads(); }
        float stdv = sqrtf(red[0] * (1.0f / L_LEN)) + EPSF;
        if (l < 128) {
            float sn = d / stdv;
            __half h = __float2half(sn);
            unsigned short hu;
            memcpy(&hu, &h, 2);
            th[l] = hu;
        }
        __syncthreads();
        if (l < 64)
            g_s16[f * 64 + l] = (uint32_t)th[2 * l] | ((uint32_t)th[2 * l + 1] << 16);
    } else {
        // ---- per-batch x prep: fp16 convert + prefix sums via warp scans ----
        const int b   = bid - NF;
        const int lid = tid & 31;
        const int wd  = tid >> 5;
        __shared__ float P[T_LEN + 1];
        __shared__ float P2[T_LEN + 1];
        __shared__ float wsum[8], wsum2[8];

        const int base = tid * 16;
        float lx[16];
        // vectorized load + fp16 store
        #pragma unroll
        for (int j = 0; j < 16; j += 4) {
            float4 v4 = *(const float4*)&x[b * T_LEN + base + j];
            lx[j] = v4.x; lx[j + 1] = v4.y; lx[j + 2] = v4.z; lx[j + 3] = v4.w;
            *(__half2*)&g_x16[b * TPAD + base + j]     = __floats2half2_rn(v4.x, v4.y);
            *(__half2*)&g_x16[b * TPAD + base + j + 2] = __floats2half2_rn(v4.z, v4.w);
        }
        if (tid < (TPAD - T_LEN) / 2)
            *(__half2*)&g_x16[b * TPAD + T_LEN + tid * 2] = __floats2half2_rn(0.f, 0.f);

        float s = 0.0f, s2 = 0.0f;
        #pragma unroll
        for (int j = 0; j < 16; ++j) {
            s += lx[j];
            s2 = fmaf(lx[j], lx[j], s2);
        }
        // warp inclusive scan (5 shfl steps, no barriers)
        float i1 = s, i2 = s2;
        #pragma unroll
        for (int off = 1; off < 32; off <<= 1) {
            float a1 = __shfl_up_sync(0xffffffffu, i1, off);
            float a2 = __shfl_up_sync(0xffffffffu, i2, off);
            if (lid >= off) { i1 += a1; i2 += a2; }
        }
        if (lid == 31) { wsum[wd] = i1; wsum2[wd] = i2; }
        __syncthreads();
        // scan the 8 warp totals in warp 0
        if (wd == 0 && lid < 8) {
            float w1 = wsum[lid], w2 = wsum2[lid];
            #pragma unroll
            for (int off = 1; off < 8; off <<= 1) {
                float a1 = __shfl_up_sync(0xffu, w1, off);
                float a2 = __shfl_up_sync(0xffu, w2, off);
                if (lid >= off) { w1 += a1; w2 += a2; }
            }
            wsum[lid] = w1; wsum2[lid] = w2;
        }
        __syncthreads();
        float r  = ((wd > 0) ? wsum[wd - 1]  : 0.0f) + (i1 - s);
        float r2 = ((wd > 0) ? wsum2[wd - 1] : 0.0f) + (i2 - s2);
        if (tid == 0) { P[0] = 0.0f; P2[0] = 0.0f; }
        #pragma unroll
        for (int j = 0; j < 16; ++j) {
            r  += lx[j];
            r2  = fmaf(lx[j], lx[j], r2);
            P[base + j + 1]  = r;
            P2[base + j + 1] = r2;
        }
        __syncthreads();
        const float QNAN = __int_as_float(0x7fffffff);
        #pragma unroll
        for (int j = 0; j < 16; ++j) {
            int w = base + j;
            float wsv = QNAN;   // fmaxf(m, NaN) == m -> masks invalid windows
            if (w < NWIN) {
                float su = P[w + L_LEN] - P[w];
                float qu = P2[w + L_LEN] - P2[w];
                float mu = su * (1.0f / L_LEN);
                float var = fmaxf(qu * (1.0f / L_LEN) - mu * mu, 0.0f);
                wsv = 1.0f / ((sqrtf(var) + EPSF) * (float)L_LEN);
            }
            g_ws[b * T_LEN + w] = wsv;
        }
    }
}

// ============================================================
// Kernel 2: main mma kernel. CTA = (tile-group, batch): 512 windows.
// 8 warps = 2 (M=64) x 4 (N=32). A frags via Hankel chain from
// 8 parity-shifted x copies. No A tile, no mainloop syncs.
// ============================================================
__global__ __launch_bounds__(256, 2)
void shapelet_mma_kernel() {
    extern __shared__ char smem[];
    const uint32_t sbase = smem_to_u32(smem);

    const int tg  = blockIdx.x;        // 0..7
    const int b   = blockIdx.y;        // 0..255
    const int tid = threadIdx.x;
    const int lid = tid & 31;
    const int wid = tid >> 5;
    const int warpRow = wid >> 2;      // 0..1 (64 windows)
    const int warpCol = wid & 3;       // 0..3 (32 filters)
    const int t0g = tg * (TPC * TW);   // 0..3584

    float* ws   = (float*)(smem + OFF_WS);
    float* wmax = (float*)(smem + OFF_WMAX);

    // ---- B tile (once) ----
    {
        uint32_t* bt = (uint32_t*)(smem + OFF_B);
        #pragma unroll
        for (int k = 0; k < 32; ++k) {
            int idx = tid + k * 256;
            int f = idx >> 6, cc = idx & 63;
            bt[f * (LDA / 2) + cc] = g_s16[idx];
        }
    }

    // ---- 8 parity-shifted x copies (once, covers all 4 tiles: 640 halfs) ----
    {
        const uint32_t* gx = (const uint32_t*)g_x16;
        const int xrow = b * (TPAD / 2);
        #pragma unroll
        for (int s = 0; s < 8; ++s) {
            uint32_t* dst = (uint32_t*)(smem + OFF_XC + s * 1296);
            if ((s & 1) == 0) {
                int gb = xrow + (t0g + s) / 2;
                dst[tid] = gx[gb + tid];
                if (tid < 64) dst[256 + tid] = gx[gb + 256 + tid];
            } else {
                int gb = xrow + (t0g + s - 1) / 2;
                uint32_t lo = gx[gb + tid], hi = gx[gb + tid + 1];
                dst[tid] = __funnelshift_r(lo, hi, 16);
                if (tid < 64) {
                    uint32_t lo2 = gx[gb + 256 + tid], hi2 = gx[gb + 257 + tid];
                    dst[256 + tid] = __funnelshift_r(lo2, hi2, 16);
                }
            }
        }
    }

    // ---- window scales for the 512-window range ----
    ws[tid]       = g_ws[b * T_LEN + t0g + tid];
    ws[256 + tid] = g_ws[b * T_LEN + t0g + 256 + tid];
    __syncthreads();

    // ---- lane bases ----
    const int quad = lid >> 3, r8 = lid & 7;
    const int w0 = warpRow * 64 + (quad & 1) * 8 + r8;       // w0 & 7 == r8
    const uint32_t aBase = sbase + OFF_XC + r8 * 1296 + (w0 - r8) * 2 + (quad >> 1) * 16;
    const uint32_t bB = sbase + OFF_B +
        ((warpCol * 32 + (quad >> 1) * 8 + r8) * LDA + (quad & 1) * 8) * 2;
    const int g = lid >> 2, tig = lid & 3;

    float m[4][2];
    #pragma unroll
    for (int nt = 0; nt < 4; ++nt) { m[nt][0] = -INFINITY; m[nt][1] = -INFINITY; }

    for (int it = 0; it < TPC; ++it) {
        const uint32_t aB = aBase + it * 256;     // +128 windows = +256 B

        float c[4][4][4];
        #pragma unroll
        for (int mt = 0; mt < 4; ++mt)
            #pragma unroll
            for (int nt = 0; nt < 4; ++nt)
                #pragma unroll
                for (int r = 0; r < 4; ++r) c[mt][nt][r] = 0.0f;

        // Hankel ring: fr[j mod 4] = A-frag(window-block 0, k-block j)
        uint32_t fr[4][4];
        ldsm_x4(fr[0], aB);
        ldsm_x4(fr[1], aB + 32);
        ldsm_x4(fr[2], aB + 64);

        #pragma unroll
        for (int ks = 0; ks < 8; ++ks) {
            ldsm_x4(fr[(ks + 3) & 3], aB + (ks + 3) * 32);
            uint32_t bb[2][4];
            ldsm_x4(bb[0], bB + ks * 32);
            ldsm_x4(bb[1], bB + 16 * LDA * 2 + ks * 32);
            #pragma unroll
            for (int mt = 0; mt < 4; ++mt) {
                const uint32_t* a = fr[(ks + mt) & 3];   // A(mt*16, ks*16) == A(0,(ks+mt)*16)
                mma_fp16(c[mt][0], a, &bb[0][0]);
                mma_fp16(c[mt][1], a, &bb[0][2]);
                mma_fp16(c[mt][2], a, &bb[1][0]);
                mma_fp16(c[mt][3], a, &bb[1][2]);
            }
        }

        // ---- fold: scale + running max (NaN scale masks invalid windows) ----
        #pragma unroll
        for (int mt = 0; mt < 4; ++mt)
            #pragma unroll
            for (int h = 0; h < 2; ++h) {
                int row = warpRow * 64 + mt * 16 + g + h * 8;
                float sc = ws[it * 128 + row];
                #pragma unroll
                for (int nt = 0; nt < 4; ++nt)
                    #pragma unroll
                    for (int d = 0; d < 2; ++d)
                        m[nt][d] = fmaxf(m[nt][d], c[mt][nt][h * 2 + d] * sc);
            }
    }

    // ---- reduce: shfl across row-groups, smem across warpRows ----
    #pragma unroll
    for (int nt = 0; nt < 4; ++nt)
        #pragma unroll
        for (int d = 0; d < 2; ++d) {
            float v = m[nt][d];
            #pragma unroll
            for (int off = 4; off < 32; off <<= 1)
                v = fmaxf(v, __shfl_xor_sync(0xffffffffu, v, off));
            m[nt][d] = v;
        }
    if (g == 0) {
        #pragma unroll
        for (int nt = 0; nt < 4; ++nt)
            #pragma unroll
            for (int d = 0; d < 2; ++d)
                wmax[warpRow * NF + warpCol * 32 + nt * 8 + tig * 2 + d] = m[nt][d];
    }
    __syncthreads();
    if (tid < NF) {
        float mm = fmaxf(wmax[tid], wmax[NF + tid]);
        g_scratch[(b * NTG + tg) * NF + tid] = mm;
    }
}

// ============================================================
// Kernel 3: final max over tile-groups
// ============================================================
__global__ void reduce_max_kernel(float* __restrict__ out) {
    const int b = blockIdx.x;
    const int f = threadIdx.x;
    float m = -INFINITY;
    #pragma unroll
    for (int t = 0; t < NTG; ++t)
        m = fmaxf(m, g_scratch[(b * NTG + t) * NF + f]);
    out[b * NF + f] = m;
}

extern "C" void kernel_launch(void* const* d_in, const int* in_sizes, int n_in,
                              void* d_out, int out_size) {
    const float* x  = (const float*)d_in[0];   // (256, 4096) fp32
    const float* sh = (const float*)d_in[1];   // (8, 16, 128) fp32
    float* out = (float*)d_out;                // (256, 128) fp32

    cudaFuncSetAttribute(shapelet_mma_kernel,
                         cudaFuncAttributeMaxDynamicSharedMemorySize, SMEM_DYN);

    prep_all_kernel<<<NF + B_SZ, 256>>>(x, sh);
    dim3 grid(NTG, B_SZ);
    shapelet_mma_kernel<<<grid, 256, SMEM_DYN>>>();
    reduce_max_kernel<<<B_SZ, NF>>>(out);
}

// round 10
// speedup vs baseline: 12.7762x; 1.2790x over previous
#include <cuda_runtime.h>
#include <cuda_fp16.h>
#include <math.h>
#include <stdint.h>
#include <string.h>

#define T_LEN   4096
#define L_LEN   128
#define NF      128
#define NWIN    3969
#define B_SZ    256
#define TW      128         // windows per tile
#define NTG     8           // tile-groups per batch (512 windows each)
#define TPC     4           // tiles per CTA
#define EPSF    1e-6f
#define LDA     136         // padded B row stride (halfs) -> 272B

// ---------------- device scratch ----------------
__device__ float    g_scratch[B_SZ * NTG * NF];
__device__ uint32_t g_s16[NF * 64];          // s_norm fp16x2 [f][k/2]

// ---------------- smem layout (main kernel, bytes) ----------------
#define OFF_B     0          // 128 x 136 half = 34816
#define OFF_XC    34816      // 8 copies x 1296 B = 10368 (stride%128==16 -> conflict-free)
#define OFF_WS    45184      // float[512] = 2048
#define OFF_WMAX  47232      // float[2][128] = 1024
#define OFF_XS    48256      // float[656] = 2624
#define OFF_XH    50880      // half[656] -> 1312 (u32-aligned)
#define OFF_P     52192      // float[641] -> 2576
#define OFF_P2    54768      // float[641] -> 2576
#define SMEM_DYN  57344

__device__ __forceinline__ uint32_t smem_to_u32(const void* p) {
    uint32_t a;
    asm("{ .reg .u64 t; cvta.to.shared.u64 t, %1; cvt.u32.u64 %0, t; }" : "=r"(a) : "l"(p));
    return a;
}
__device__ __forceinline__ void ldsm_x4(uint32_t* r, uint32_t addr) {
    asm volatile("ldmatrix.sync.aligned.m8n8.x4.shared.b16 {%0,%1,%2,%3}, [%4];"
                 : "=r"(r[0]), "=r"(r[1]), "=r"(r[2]), "=r"(r[3]) : "r"(addr));
}
__device__ __forceinline__ void mma_fp16(float* c, const uint32_t* a, const uint32_t* b) {
    asm volatile(
        "mma.sync.aligned.m16n8k16.row.col.f32.f16.f16.f32 "
        "{%0,%1,%2,%3}, {%4,%5,%6,%7}, {%8,%9}, {%0,%1,%2,%3};"
        : "+f"(c[0]), "+f"(c[1]), "+f"(c[2]), "+f"(c[3])
        : "r"(a[0]), "r"(a[1]), "r"(a[2]), "r"(a[3]), "r"(b[0]), "r"(b[1]));
}

// ============================================================
// Kernel 1: z-normalize shapelets -> fp16 packed (tiny)
// ============================================================
__global__ void prep_snorm_kernel(const float* __restrict__ sh) {
    const int f = blockIdx.x;
    const int l = threadIdx.x;
    __shared__ float red[128];
    __shared__ unsigned short th[128];

    float v = sh[f * L_LEN + l];
    red[l] = v;
    __syncthreads();
    #pragma unroll
    for (int s = 64; s > 0; s >>= 1) { if (l < s) red[l] += red[l + s]; __syncthreads(); }
    float mu = red[0] * (1.0f / L_LEN);
    __syncthreads();
    float d = v - mu;
    red[l] = d * d;
    __syncthreads();
    #pragma unroll
    for (int s = 64; s > 0; s >>= 1) { if (l < s) red[l] += red[l + s]; __syncthreads(); }
    float stdv = sqrtf(red[0] * (1.0f / L_LEN)) + EPSF;
    float sn = d / stdv;
    __half h = __float2half(sn);
    unsigned short hu;
    memcpy(&hu, &h, 2);
    th[l] = hu;
    __syncthreads();
    if (l < 64)
        g_s16[f * 64 + l] = (uint32_t)th[2 * l] | ((uint32_t)th[2 * l + 1] << 16);
}

// ============================================================
// Kernel 2: main mma kernel with in-CTA x prep.
// CTA = (tile-group, batch): 512 windows. 8 warps = 2(M=64) x 4(N=32).
// ============================================================
__global__ __launch_bounds__(256, 2)
void shapelet_mma_kernel(const float* __restrict__ x) {
    extern __shared__ char smem[];
    const uint32_t sbase = smem_to_u32(smem);

    const int tg  = blockIdx.x;        // 0..7
    const int b   = blockIdx.y;        // 0..255
    const int tid = threadIdx.x;
    const int lid = tid & 31;
    const int wid = tid >> 5;
    const int warpRow = wid >> 2;      // 0..1 (64 windows)
    const int warpCol = wid & 3;       // 0..3 (32 filters)
    const int t0g = tg * (TPC * TW);   // 0..3584

    float*    ws   = (float*)(smem + OFF_WS);
    float*    wmax = (float*)(smem + OFF_WMAX);
    float*    xs   = (float*)(smem + OFF_XS);
    uint32_t* xh32 = (uint32_t*)(smem + OFF_XH);
    float*    P    = (float*)(smem + OFF_P);
    float*    P2   = (float*)(smem + OFF_P2);
    __shared__ float wsum[8], wsum2[8];

    // ---- load raw x fp32 slice (656, zero-padded) ----
    #pragma unroll
    for (int i = tid; i < 656; i += 256) {
        int t = t0g + i;
        xs[i] = (t < T_LEN) ? x[b * T_LEN + t] : 0.0f;
    }

    // ---- B tile (once) ----
    {
        uint32_t* bt = (uint32_t*)(smem + OFF_B);
        #pragma unroll
        for (int k = 0; k < 32; ++k) {
            int idx = tid + k * 256;
            int f = idx >> 6, cc = idx & 63;
            bt[f * (LDA / 2) + cc] = g_s16[idx];
        }
    }
    __syncthreads();

    // ---- prefix scan of (x, x^2) over 640 slice elems (3 per thread) ----
    {
        const int e0 = 3 * tid;
        float l0 = (e0     < 648) ? xs[e0]     : 0.0f;
        float l1 = (e0 + 1 < 648) ? xs[e0 + 1] : 0.0f;
        float l2 = (e0 + 2 < 648) ? xs[e0 + 2] : 0.0f;
        float s  = l0 + l1 + l2;
        float s2 = fmaf(l0, l0, fmaf(l1, l1, l2 * l2));
        float i1 = s, i2 = s2;
        #pragma unroll
        for (int off = 1; off < 32; off <<= 1) {
            float a1 = __shfl_up_sync(0xffffffffu, i1, off);
            float a2 = __shfl_up_sync(0xffffffffu, i2, off);
            if (lid >= off) { i1 += a1; i2 += a2; }
        }
        if (lid == 31) { wsum[wid] = i1; wsum2[wid] = i2; }
        __syncthreads();
        if (wid == 0 && lid < 8) {
            float w1 = wsum[lid], w2 = wsum2[lid];
            #pragma unroll
            for (int off = 1; off < 8; off <<= 1) {
                float a1 = __shfl_up_sync(0xffu, w1, off);
                float a2 = __shfl_up_sync(0xffu, w2, off);
                if (lid >= off) { w1 += a1; w2 += a2; }
            }
            wsum[lid] = w1; wsum2[lid] = w2;
        }
        __syncthreads();
        float r  = ((wid > 0) ? wsum[wid - 1]  : 0.0f) + (i1 - s);
        float r2 = ((wid > 0) ? wsum2[wid - 1] : 0.0f) + (i2 - s2);
        if (tid == 0) { P[0] = 0.0f; P2[0] = 0.0f; }
        r += l0; r2 = fmaf(l0, l0, r2);
        if (e0 + 1 <= 640) { P[e0 + 1] = r; P2[e0 + 1] = r2; }
        r += l1; r2 = fmaf(l1, l1, r2);
        if (e0 + 2 <= 640) { P[e0 + 2] = r; P2[e0 + 2] = r2; }
        r += l2; r2 = fmaf(l2, l2, r2);
        if (e0 + 3 <= 640) { P[e0 + 3] = r; P2[e0 + 3] = r2; }
    }

    // ---- fp16 convert into xh (no barrier needed before: xs already synced) ----
    #pragma unroll
    for (int t = tid; t < 324; t += 256)
        xh32[t] = __half2_raw(__floats2half2_rn(xs[2 * t], xs[2 * t + 1])).x |
                  ((uint32_t)__half2_raw(__floats2half2_rn(xs[2 * t], xs[2 * t + 1])).y << 16);
    __syncthreads();

    // ---- window scales (NaN masks invalid windows via fmaxf semantics) ----
    {
        const float QNAN = __int_as_float(0x7fffffff);
        #pragma unroll
        for (int w = tid; w < 512; w += 256) {
            float wsv = QNAN;
            if (t0g + w < NWIN) {
                float su = P[w + L_LEN] - P[w];
                float qu = P2[w + L_LEN] - P2[w];
                float mu = su * (1.0f / L_LEN);
                float var = fmaxf(qu * (1.0f / L_LEN) - mu * mu, 0.0f);
                wsv = 1.0f / ((sqrtf(var) + EPSF) * (float)L_LEN);
            }
            ws[w] = wsv;
        }
    }

    // ---- 8 parity-shifted x copies from xh ----
    #pragma unroll
    for (int s = 0; s < 8; ++s) {
        uint32_t* dst = (uint32_t*)(smem + OFF_XC + s * 1296);
        if ((s & 1) == 0) {
            const int gb = s >> 1;
            dst[tid] = xh32[gb + tid];
            if (tid < 64) dst[256 + tid] = xh32[gb + 256 + tid];
        } else {
            const int gb = (s - 1) >> 1;
            dst[tid] = __funnelshift_r(xh32[gb + tid], xh32[gb + tid + 1], 16);
            if (tid < 64)
                dst[256 + tid] = __funnelshift_r(xh32[gb + 256 + tid], xh32[gb + 257 + tid], 16);
        }
    }
    __syncthreads();

    // ---- lane bases ----
    const int quad = lid >> 3, r8 = lid & 7;
    const int w0 = warpRow * 64 + (quad & 1) * 8 + r8;       // w0 & 7 == r8
    const uint32_t aBase = sbase + OFF_XC + r8 * 1296 + (w0 - r8) * 2 + (quad >> 1) * 16;
    const uint32_t bB = sbase + OFF_B +
        ((warpCol * 32 + (quad >> 1) * 8 + r8) * LDA + (quad & 1) * 8) * 2;
    const int g = lid >> 2, tig = lid & 3;

    float m[4][2];
    #pragma unroll
    for (int nt = 0; nt < 4; ++nt) { m[nt][0] = -INFINITY; m[nt][1] = -INFINITY; }

    for (int it = 0; it < TPC; ++it) {
        const uint32_t aB = aBase + it * 256;     // +128 windows = +256 B

        float c[4][4][4];
        #pragma unroll
        for (int mt = 0; mt < 4; ++mt)
            #pragma unroll
            for (int nt = 0; nt < 4; ++nt)
                #pragma unroll
                for (int r = 0; r < 4; ++r) c[mt][nt][r] = 0.0f;

        // Hankel ring: fr[j mod 4] = A-frag(window-block 0, k-block j)
        uint32_t fr[4][4];
        ldsm_x4(fr[0], aB);
        ldsm_x4(fr[1], aB + 32);
        ldsm_x4(fr[2], aB + 64);

        #pragma unroll
        for (int ks = 0; ks < 8; ++ks) {
            ldsm_x4(fr[(ks + 3) & 3], aB + (ks + 3) * 32);
            uint32_t bb[2][4];
            ldsm_x4(bb[0], bB + ks * 32);
            ldsm_x4(bb[1], bB + 16 * LDA * 2 + ks * 32);
            #pragma unroll
            for (int mt = 0; mt < 4; ++mt) {
                const uint32_t* a = fr[(ks + mt) & 3];   // A(mt*16, ks*16) == A(0,(ks+mt)*16)
                mma_fp16(c[mt][0], a, &bb[0][0]);
                mma_fp16(c[mt][1], a, &bb[0][2]);
                mma_fp16(c[mt][2], a, &bb[1][0]);
                mma_fp16(c[mt][3], a, &bb[1][2]);
            }
        }

        // ---- fold: scale + running max (NaN scale masks invalid windows) ----
        #pragma unroll
        for (int mt = 0; mt < 4; ++mt)
            #pragma unroll
            for (int h = 0; h < 2; ++h) {
                int row = warpRow * 64 + mt * 16 + g + h * 8;
                float sc = ws[it * 128 + row];
                #pragma unroll
                for (int nt = 0; nt < 4; ++nt)
                    #pragma unroll
                    for (int d = 0; d < 2; ++d)
                        m[nt][d] = fmaxf(m[nt][d], c[mt][nt][h * 2 + d] * sc);
            }
    }

    // ---- reduce: shfl across row-groups, smem across warpRows ----
    #pragma unroll
    for (int nt = 0; nt < 4; ++nt)
        #pragma unroll
        for (int d = 0; d < 2; ++d) {
            float v = m[nt][d];
            #pragma unroll
            for (int off = 4; off < 32; off <<= 1)
                v = fmaxf(v, __shfl_xor_sync(0xffffffffu, v, off));
            m[nt][d] = v;
        }
    if (g == 0) {
        #pragma unroll
        for (int nt = 0; nt < 4; ++nt)
            #pragma unroll
            for (int d = 0; d < 2; ++d)
                wmax[warpRow * NF + warpCol * 32 + nt * 8 + tig * 2 + d] = m[nt][d];
    }
    __syncthreads();
    if (tid < NF) {
        float mm = fmaxf(wmax[tid], wmax[NF + tid]);
        g_scratch[(b * NTG + tg) * NF + tid] = mm;
    }
}

// ============================================================
// Kernel 3: final max over tile-groups
// ============================================================
__global__ void reduce_max_kernel(float* __restrict__ out) {
    const int b = blockIdx.x;
    const int f = threadIdx.x;
    float m = -INFINITY;
    #pragma unroll
    for (int t = 0; t < NTG; ++t)
        m = fmaxf(m, g_scratch[(b * NTG + t) * NF + f]);
    out[b * NF + f] = m;
}

extern "C" void kernel_launch(void* const* d_in, const int* in_sizes, int n_in,
                              void* d_out, int out_size) {
    const float* x  = (const float*)d_in[0];   // (256, 4096) fp32
    const float* sh = (const float*)d_in[1];   // (8, 16, 128) fp32
    float* out = (float*)d_out;                // (256, 128) fp32

    cudaFuncSetAttribute(shapelet_mma_kernel,
                         cudaFuncAttributeMaxDynamicSharedMemorySize, SMEM_DYN);

    prep_snorm_kernel<<<NF, L_LEN>>>(sh);
    dim3 grid(NTG, B_SZ);
    shapelet_mma_kernel<<<grid, 256, SMEM_DYN>>>(x);
    reduce_max_kernel<<<B_SZ, NF>>>(out);
}

// round 12
// speedup vs baseline: 12.8681x; 1.0072x over previous
#include <cuda_runtime.h>
#include <cuda_fp16.h>
#include <math.h>
#include <stdint.h>
#include <string.h>

#define T_LEN   4096
#define L_LEN   128
#define NF      128
#define NWIN    3969
#define B_SZ    256
#define TW      128         // windows per tile
#define NTG     8           // tile-groups per batch (512 windows each)
#define TPC     4           // tiles per CTA
#define EPSF    1e-6f
#define LDA     136         // padded B row stride (halfs) -> 272B

// ---------------- device scratch ----------------
__device__ uint32_t g_s16[NF * 64];          // s_norm fp16x2 [f][k/2]

// ---------------- smem layout (main kernel, bytes) ----------------
#define OFF_B     0          // 128 x 136 half = 34816
#define OFF_XC    34816      // 8 copies x 1296 B = 10368 (stride%128==16 -> conflict-free)
#define OFF_WS    45184      // float[512] = 2048
#define OFF_WMAX  47232      // float[2][128] = 1024
#define OFF_XS    48256      // float[656] = 2624
#define OFF_XH    50880      // half[656] -> 1312 (u32-aligned)
#define OFF_P     52192      // float[641] -> 2576
#define OFF_P2    54768      // float[641] -> 2576
#define SMEM_DYN  57344

__device__ __forceinline__ uint32_t smem_to_u32(const void* p) {
    uint32_t a;
    asm("{ .reg .u64 t; cvta.to.shared.u64 t, %1; cvt.u32.u64 %0, t; }" : "=r"(a) : "l"(p));
    return a;
}
__device__ __forceinline__ void ldsm_x4(uint32_t* r, uint32_t addr) {
    asm volatile("ldmatrix.sync.aligned.m8n8.x4.shared.b16 {%0,%1,%2,%3}, [%4];"
                 : "=r"(r[0]), "=r"(r[1]), "=r"(r[2]), "=r"(r[3]) : "r"(addr));
}
__device__ __forceinline__ void mma_fp16(float* c, const uint32_t* a, const uint32_t* b) {
    asm volatile(
        "mma.sync.aligned.m16n8k16.row.col.f32.f16.f16.f32 "
        "{%0,%1,%2,%3}, {%4,%5,%6,%7}, {%8,%9}, {%0,%1,%2,%3};"
        : "+f"(c[0]), "+f"(c[1]), "+f"(c[2]), "+f"(c[3])
        : "r"(a[0]), "r"(a[1]), "r"(a[2]), "r"(a[3]), "r"(b[0]), "r"(b[1]));
}
// exact float atomic max via monotone int/uint encoding (init must be -inf)
__device__ __forceinline__ void atomicMaxFloat(float* addr, float value) {
    if (value >= 0.0f)
        atomicMax((int*)addr, __float_as_int(value));
    else
        atomicMin((unsigned int*)addr, __float_as_uint(value));
}

// ============================================================
// Kernel 1: z-normalize shapelets -> fp16 packed + init d_out to -inf
// ============================================================
__global__ void prep_snorm_kernel(const float* __restrict__ sh, float* __restrict__ out) {
    const int f = blockIdx.x;
    const int l = threadIdx.x;
    __shared__ float red[128];
    __shared__ unsigned short th[128];

    // init output (128 blocks x 128 threads x 2 = 32768)
    const int oi = (f * L_LEN + l) * 2;
    out[oi]     = -INFINITY;
    out[oi + 1] = -INFINITY;

    float v = sh[f * L_LEN + l];
    red[l] = v;
    __syncthreads();
    #pragma unroll
    for (int s = 64; s > 0; s >>= 1) { if (l < s) red[l] += red[l + s]; __syncthreads(); }
    float mu = red[0] * (1.0f / L_LEN);
    __syncthreads();
    float d = v - mu;
    red[l] = d * d;
    __syncthreads();
    #pragma unroll
    for (int s = 64; s > 0; s >>= 1) { if (l < s) red[l] += red[l + s]; __syncthreads(); }
    float stdv = sqrtf(red[0] * (1.0f / L_LEN)) + EPSF;
    float sn = d / stdv;
    __half h = __float2half(sn);
    unsigned short hu;
    memcpy(&hu, &h, 2);
    th[l] = hu;
    __syncthreads();
    if (l < 64)
        g_s16[f * 64 + l] = (uint32_t)th[2 * l] | ((uint32_t)th[2 * l + 1] << 16);
}

// ============================================================
// Kernel 2: main mma kernel with in-CTA x prep + atomic-max epilogue.
// CTA = (tile-group, batch): 512 windows. 8 warps = 2(M=64) x 4(N=32).
// ============================================================
__global__ __launch_bounds__(256, 2)
void shapelet_mma_kernel(const float* __restrict__ x, float* __restrict__ out) {
    extern __shared__ char smem[];
    const uint32_t sbase = smem_to_u32(smem);

    const int tg  = blockIdx.x;        // 0..7
    const int b   = blockIdx.y;        // 0..255
    const int tid = threadIdx.x;
    const int lid = tid & 31;
    const int wid = tid >> 5;
    const int warpRow = wid >> 2;      // 0..1 (64 windows)
    const int warpCol = wid & 3;       // 0..3 (32 filters)
    const int t0g = tg * (TPC * TW);   // 0..3584

    float*    ws   = (float*)(smem + OFF_WS);
    float*    wmax = (float*)(smem + OFF_WMAX);
    float*    xs   = (float*)(smem + OFF_XS);
    uint32_t* xh32 = (uint32_t*)(smem + OFF_XH);
    float*    P    = (float*)(smem + OFF_P);
    float*    P2   = (float*)(smem + OFF_P2);
    __shared__ float wsum[8], wsum2[8];

    // ---- load raw x fp32 slice (656, zero-padded) ----
    #pragma unroll
    for (int i = tid; i < 656; i += 256) {
        int t = t0g + i;
        xs[i] = (t < T_LEN) ? x[b * T_LEN + t] : 0.0f;
    }

    // ---- B tile (once) ----
    {
        uint32_t* bt = (uint32_t*)(smem + OFF_B);
        #pragma unroll
        for (int k = 0; k < 32; ++k) {
            int idx = tid + k * 256;
            int f = idx >> 6, cc = idx & 63;
            bt[f * (LDA / 2) + cc] = g_s16[idx];
        }
    }
    __syncthreads();

    // ---- prefix scan of (x, x^2) over 640 slice elems (3 per thread) ----
    {
        const int e0 = 3 * tid;
        float l0 = (e0     < 648) ? xs[e0]     : 0.0f;
        float l1 = (e0 + 1 < 648) ? xs[e0 + 1] : 0.0f;
        float l2 = (e0 + 2 < 648) ? xs[e0 + 2] : 0.0f;
        float s  = l0 + l1 + l2;
        float s2 = fmaf(l0, l0, fmaf(l1, l1, l2 * l2));
        float i1 = s, i2 = s2;
        #pragma unroll
        for (int off = 1; off < 32; off <<= 1) {
            float a1 = __shfl_up_sync(0xffffffffu, i1, off);
            float a2 = __shfl_up_sync(0xffffffffu, i2, off);
            if (lid >= off) { i1 += a1; i2 += a2; }
        }
        if (lid == 31) { wsum[wid] = i1; wsum2[wid] = i2; }
        __syncthreads();
        if (wid == 0 && lid < 8) {
            float w1 = wsum[lid], w2 = wsum2[lid];
            #pragma unroll
            for (int off = 1; off < 8; off <<= 1) {
                float a1 = __shfl_up_sync(0xffu, w1, off);
                float a2 = __shfl_up_sync(0xffu, w2, off);
                if (lid >= off) { w1 += a1; w2 += a2; }
            }
            wsum[lid] = w1; wsum2[lid] = w2;
        }
        __syncthreads();
        float r  = ((wid > 0) ? wsum[wid - 1]  : 0.0f) + (i1 - s);
        float r2 = ((wid > 0) ? wsum2[wid - 1] : 0.0f) + (i2 - s2);
        if (tid == 0) { P[0] = 0.0f; P2[0] = 0.0f; }
        r += l0; r2 = fmaf(l0, l0, r2);
        if (e0 + 1 <= 640) { P[e0 + 1] = r; P2[e0 + 1] = r2; }
        r += l1; r2 = fmaf(l1, l1, r2);
        if (e0 + 2 <= 640) { P[e0 + 2] = r; P2[e0 + 2] = r2; }
        r += l2; r2 = fmaf(l2, l2, r2);
        if (e0 + 3 <= 640) { P[e0 + 3] = r; P2[e0 + 3] = r2; }
    }

    // ---- fp16 convert into xh ----
    #pragma unroll
    for (int t = tid; t < 324; t += 256) {
        __half2 h2 = __floats2half2_rn(xs[2 * t], xs[2 * t + 1]);
        xh32[t] = *(uint32_t*)&h2;
    }
    __syncthreads();

    // ---- window scales (NaN masks invalid windows via fmaxf semantics) ----
    {
        const float QNAN = __int_as_float(0x7fffffff);
        #pragma unroll
        for (int w = tid; w < 512; w += 256) {
            float wsv = QNAN;
            if (t0g + w < NWIN) {
                float su = P[w + L_LEN] - P[w];
                float qu = P2[w + L_LEN] - P2[w];
                float mu = su * (1.0f / L_LEN);
                float var = fmaxf(qu * (1.0f / L_LEN) - mu * mu, 0.0f);
                wsv = 1.0f / ((sqrtf(var) + EPSF) * (float)L_LEN);
            }
            ws[w] = wsv;
        }
    }

    // ---- 8 parity-shifted x copies from xh ----
    #pragma unroll
    for (int s = 0; s < 8; ++s) {
        uint32_t* dst = (uint32_t*)(smem + OFF_XC + s * 1296);
        if ((s & 1) == 0) {
            const int gb = s >> 1;
            dst[tid] = xh32[gb + tid];
            if (tid < 64) dst[256 + tid] = xh32[gb + 256 + tid];
        } else {
            const int gb = (s - 1) >> 1;
            dst[tid] = __funnelshift_r(xh32[gb + tid], xh32[gb + tid + 1], 16);
            if (tid < 64)
                dst[256 + tid] = __funnelshift_r(xh32[gb + 256 + tid], xh32[gb + 257 + tid], 16);
        }
    }
    __syncthreads();

    // ---- lane bases ----
    const int quad = lid >> 3, r8 = lid & 7;
    const int w0 = warpRow * 64 + (quad & 1) * 8 + r8;       // w0 & 7 == r8
    const uint32_t aBase = sbase + OFF_XC + r8 * 1296 + (w0 - r8) * 2 + (quad >> 1) * 16;
    const uint32_t bB = sbase + OFF_B +
        ((warpCol * 32 + (quad >> 1) * 8 + r8) * LDA + (quad & 1) * 8) * 2;
    const int g = lid >> 2, tig = lid & 3;

    float m[4][2];
    #pragma unroll
    for (int nt = 0; nt < 4; ++nt) { m[nt][0] = -INFINITY; m[nt][1] = -INFINITY; }

    for (int it = 0; it < TPC; ++it) {
        const uint32_t aB = aBase + it * 256;     // +128 windows = +256 B

        float c[4][4][4];
        #pragma unroll
        for (int mt = 0; mt < 4; ++mt)
            #pragma unroll
            for (int nt = 0; nt < 4; ++nt)
                #pragma unroll
                for (int r = 0; r < 4; ++r) c[mt][nt][r] = 0.0f;

        // Hankel ring: fr[j mod 4] = A-frag(window-block 0, k-block j)
        uint32_t fr[4][4];
        ldsm_x4(fr[0], aB);
        ldsm_x4(fr[1], aB + 32);
        ldsm_x4(fr[2], aB + 64);

        #pragma unroll
        for (int ks = 0; ks < 8; ++ks) {
            ldsm_x4(fr[(ks + 3) & 3], aB + (ks + 3) * 32);
            uint32_t bb[2][4];
            ldsm_x4(bb[0], bB + ks * 32);
            ldsm_x4(bb[1], bB + 16 * LDA * 2 + ks * 32);
            #pragma unroll
            for (int mt = 0; mt < 4; ++mt) {
                const uint32_t* a = fr[(ks + mt) & 3];   // A(mt*16, ks*16) == A(0,(ks+mt)*16)
                mma_fp16(c[mt][0], a, &bb[0][0]);
                mma_fp16(c[mt][1], a, &bb[0][2]);
                mma_fp16(c[mt][2], a, &bb[1][0]);
                mma_fp16(c[mt][3], a, &bb[1][2]);
            }
        }

        // ---- fold: scale + running max (NaN scale masks invalid windows) ----
        #pragma unroll
        for (int mt = 0; mt < 4; ++mt)
            #pragma unroll
            for (int h = 0; h < 2; ++h) {
                int row = warpRow * 64 + mt * 16 + g + h * 8;
                float sc = ws[it * 128 + row];
                #pragma unroll
                for (int nt = 0; nt < 4; ++nt)
                    #pragma unroll
                    for (int d = 0; d < 2; ++d)
                        m[nt][d] = fmaxf(m[nt][d], c[mt][nt][h * 2 + d] * sc);
            }
    }

    // ---- reduce: shfl across row-groups, smem across warpRows, atomic out ----
    #pragma unroll
    for (int nt = 0; nt < 4; ++nt)
        #pragma unroll
        for (int d = 0; d < 2; ++d) {
            float v = m[nt][d];
            #pragma unroll
            for (int off = 4; off < 32; off <<= 1)
                v = fmaxf(v, __shfl_xor_sync(0xffffffffu, v, off));
            m[nt][d] = v;
        }
    if (g == 0) {
        #pragma unroll
        for (int nt = 0; nt < 4; ++nt)
            #pragma unroll
            for (int d = 0; d < 2; ++d)
                wmax[warpRow * NF + warpCol * 32 + nt * 8 + tig * 2 + d] = m[nt][d];
    }
    __syncthreads();
    if (tid < NF) {
        float mm = fmaxf(wmax[tid], wmax[NF + tid]);
        atomicMaxFloat(&out[b * NF + tid], mm);
    }
}

extern "C" void kernel_launch(void* const* d_in, const int* in_sizes, int n_in,
                              void* d_out, int out_size) {
    const float* x  = (const float*)d_in[0];   // (256, 4096) fp32
    const float* sh = (const float*)d_in[1];   // (8, 16, 128) fp32
    float* out = (float*)d_out;                // (256, 128) fp32

    cudaFuncSetAttribute(shapelet_mma_kernel,
                         cudaFuncAttributeMaxDynamicSharedMemorySize, SMEM_DYN);

    prep_snorm_kernel<<<NF, L_LEN>>>(sh, out);
    dim3 grid(NTG, B_SZ);
    shapelet_mma_kernel<<<grid, 256, SMEM_DYN>>>(x, out);
}

// round 17
// speedup vs baseline: 13.2113x; 1.0267x over previous
#include <cuda_runtime.h>
#include <cuda_fp16.h>
#include <math.h>
#include <stdint.h>
#include <string.h>

#define T_LEN   4096
#define L_LEN   128
#define NF      128
#define NWIN    3969
#define B_SZ    256
#define TW      128         // windows per tile
#define NTG     4           // tile-groups per batch (1024 windows each)
#define TPC     8           // tiles per CTA
#define EPSF    1e-6f
#define LDA     136         // padded B row stride (halfs) -> 272B

// ---------------- device scratch ----------------
__device__ uint32_t g_s16[NF * 64];          // s_norm fp16x2 [f][k/2]

// ---------------- smem layout (main kernel, bytes) ----------------
// XC copy stride 2320 B (mod 128 == 16 -> conflict-free ldsm across copies)
#define OFF_B     0          // 128 x 136 half = 34816
#define OFF_XC    34816      // 8 copies x 2320 B = 18560
#define OFF_WS    53376      // float[1024] = 4096
#define OFF_WMAX  57472      // float[2][128] = 1024
#define OFF_XS    58496      // float[1160] = 4640
#define OFF_XH    63136      // u32[580] = 2320
#define OFF_P     65456      // float[1156] = 4624
#define OFF_P2    70080      // float[1156] = 4624
#define SMEM_DYN  74752

__device__ __forceinline__ uint32_t smem_to_u32(const void* p) {
    uint32_t a;
    asm("{ .reg .u64 t; cvta.to.shared.u64 t, %1; cvt.u32.u64 %0, t; }" : "=r"(a) : "l"(p));
    return a;
}
__device__ __forceinline__ void ldsm_x4(uint32_t* r, uint32_t addr) {
    asm volatile("ldmatrix.sync.aligned.m8n8.x4.shared.b16 {%0,%1,%2,%3}, [%4];"
                 : "=r"(r[0]), "=r"(r[1]), "=r"(r[2]), "=r"(r[3]) : "r"(addr));
}
__device__ __forceinline__ void mma_fp16(float* c, const uint32_t* a, const uint32_t* b) {
    asm volatile(
        "mma.sync.aligned.m16n8k16.row.col.f32.f16.f16.f32 "
        "{%0,%1,%2,%3}, {%4,%5,%6,%7}, {%8,%9}, {%0,%1,%2,%3};"
        : "+f"(c[0]), "+f"(c[1]), "+f"(c[2]), "+f"(c[3])
        : "r"(a[0]), "r"(a[1]), "r"(a[2]), "r"(a[3]), "r"(b[0]), "r"(b[1]));
}
// exact float atomic max via monotone int/uint encoding (init must be -inf)
__device__ __forceinline__ void atomicMaxFloat(float* addr, float value) {
    if (value >= 0.0f)
        atomicMax((int*)addr, __float_as_int(value));
    else
        atomicMin((unsigned int*)addr, __float_as_uint(value));
}

// ============================================================
// Kernel 1: z-normalize shapelets -> fp16 packed + init d_out to -inf
// ============================================================
__global__ void prep_snorm_kernel(const float* __restrict__ sh, float* __restrict__ out) {
    const int f = blockIdx.x;
    const int l = threadIdx.x;
    __shared__ float red[128];
    __shared__ unsigned short th[128];

    const int oi = (f * L_LEN + l) * 2;
    out[oi]     = -INFINITY;
    out[oi + 1] = -INFINITY;

    float v = sh[f * L_LEN + l];
    red[l] = v;
    __syncthreads();
    #pragma unroll
    for (int s = 64; s > 0; s >>= 1) { if (l < s) red[l] += red[l + s]; __syncthreads(); }
    float mu = red[0] * (1.0f / L_LEN);
    __syncthreads();
    float d = v - mu;
    red[l] = d * d;
    __syncthreads();
    #pragma unroll
    for (int s = 64; s > 0; s >>= 1) { if (l < s) red[l] += red[l + s]; __syncthreads(); }
    float stdv = sqrtf(red[0] * (1.0f / L_LEN)) + EPSF;
    float sn = d / stdv;
    __half h = __float2half(sn);
    unsigned short hu;
    memcpy(&hu, &h, 2);
    th[l] = hu;
    __syncthreads();
    if (l < 64)
        g_s16[f * 64 + l] = (uint32_t)th[2 * l] | ((uint32_t)th[2 * l + 1] << 16);
}

// ============================================================
// Kernel 2: main mma kernel. CTA = (tile-group, batch): 1024 windows,
// 8 tiles. 8 warps = 2(M=64) x 4(N=32). In-CTA x prep, Hankel A frags,
// atomic-max epilogue.
// ============================================================
__global__ __launch_bounds__(256, 2)
void shapelet_mma_kernel(const float* __restrict__ x, float* __restrict__ out) {
    extern __shared__ char smem[];
    const uint32_t sbase = smem_to_u32(smem);

    const int tg  = blockIdx.x;        // 0..3
    const int b   = blockIdx.y;        // 0..255
    const int tid = threadIdx.x;
    const int lid = tid & 31;
    const int wid = tid >> 5;
    const int warpRow = wid >> 2;      // 0..1 (64 windows)
    const int warpCol = wid & 3;       // 0..3 (32 filters)
    const int t0g = tg * (TPC * TW);   // 0,1024,2048,3072

    float*    ws   = (float*)(smem + OFF_WS);
    float*    wmax = (float*)(smem + OFF_WMAX);
    float*    xs   = (float*)(smem + OFF_XS);
    uint32_t* xh32 = (uint32_t*)(smem + OFF_XH);
    float*    P    = (float*)(smem + OFF_P);
    float*    P2   = (float*)(smem + OFF_P2);
    __shared__ float wsum[8], wsum2[8];

    // ---- load raw x fp32 slice (1160, zero-padded) ----
    #pragma unroll
    for (int i = tid; i < 1160; i += 256) {
        int t = t0g + i;
        xs[i] = (t < T_LEN) ? x[b * T_LEN + t] : 0.0f;
    }

    // ---- B tile (once) ----
    {
        uint32_t* bt = (uint32_t*)(smem + OFF_B);
        #pragma unroll
        for (int k = 0; k < 32; ++k) {
            int idx = tid + k * 256;
            int f = idx >> 6, cc = idx & 63;
            bt[f * (LDA / 2) + cc] = g_s16[idx];
        }
    }
    __syncthreads();

    // ---- prefix scan of (x, x^2) over 1152 slice elems (5 per thread) ----
    {
        const int e0 = 5 * tid;
        float lx[5];
        float s = 0.0f, s2 = 0.0f;
        #pragma unroll
        for (int j = 0; j < 5; ++j) {
            float v = (e0 + j < 1160) ? xs[e0 + j] : 0.0f;
            lx[j] = v;
            s += v;
            s2 = fmaf(v, v, s2);
        }
        float i1 = s, i2 = s2;
        #pragma unroll
        for (int off = 1; off < 32; off <<= 1) {
            float a1 = __shfl_up_sync(0xffffffffu, i1, off);
            float a2 = __shfl_up_sync(0xffffffffu, i2, off);
            if (lid >= off) { i1 += a1; i2 += a2; }
        }
        if (lid == 31) { wsum[wid] = i1; wsum2[wid] = i2; }
        __syncthreads();
        if (wid == 0 && lid < 8) {
            float w1 = wsum[lid], w2 = wsum2[lid];
            #pragma unroll
            for (int off = 1; off < 8; off <<= 1) {
                float a1 = __shfl_up_sync(0xffu, w1, off);
                float a2 = __shfl_up_sync(0xffu, w2, off);
                if (lid >= off) { w1 += a1; w2 += a2; }
            }
            wsum[lid] = w1; wsum2[lid] = w2;
        }
        __syncthreads();
        float r  = ((wid > 0) ? wsum[wid - 1]  : 0.0f) + (i1 - s);
        float r2 = ((wid > 0) ? wsum2[wid - 1] : 0.0f) + (i2 - s2);
        if (tid == 0) { P[0] = 0.0f; P2[0] = 0.0f; }
        #pragma unroll
        for (int j = 0; j < 5; ++j) {
            r  += lx[j];
            r2  = fmaf(lx[j], lx[j], r2);
            if (e0 + j + 1 <= 1152) { P[e0 + j + 1] = r; P2[e0 + j + 1] = r2; }
        }
    }

    // ---- fp16 convert into xh ----
    #pragma unroll
    for (int t = tid; t < 580; t += 256) {
        __half2 h2 = __floats2half2_rn(xs[2 * t], xs[2 * t + 1]);
        xh32[t] = *(uint32_t*)&h2;
    }
    __syncthreads();

    // ---- window scales (NaN masks invalid windows via fmaxf semantics) ----
    {
        const float QNAN = __int_as_float(0x7fffffff);
        #pragma unroll
        for (int w = tid; w < 1024; w += 256) {
            float wsv = QNAN;
            if (t0g + w < NWIN) {
                float su = P[w + L_LEN] - P[w];
                float qu = P2[w + L_LEN] - P2[w];
                float mu = su * (1.0f / L_LEN);
                float var = fmaxf(qu * (1.0f / L_LEN) - mu * mu, 0.0f);
                wsv = 1.0f / ((sqrtf(var) + EPSF) * (float)L_LEN);
            }
            ws[w] = wsv;
        }
    }

    // ---- 8 parity-shifted x copies from xh (576 u32 each) ----
    #pragma unroll
    for (int s = 0; s < 8; ++s) {
        uint32_t* dst = (uint32_t*)(smem + OFF_XC + s * 2320);
        if ((s & 1) == 0) {
            const int gb = s >> 1;
            #pragma unroll
            for (int i = tid; i < 576; i += 256)
                dst[i] = xh32[gb + i];
        } else {
            const int gb = (s - 1) >> 1;
            #pragma unroll
            for (int i = tid; i < 576; i += 256)
                dst[i] = __funnelshift_r(xh32[gb + i], xh32[gb + i + 1], 16);
        }
    }
    __syncthreads();

    // ---- lane bases ----
    const int quad = lid >> 3, r8 = lid & 7;
    const int w0 = warpRow * 64 + (quad & 1) * 8 + r8;       // w0 & 7 == r8
    const uint32_t aBase = sbase + OFF_XC + r8 * 2320 + (w0 - r8) * 2 + (quad >> 1) * 16;
    const uint32_t bB = sbase + OFF_B +
        ((warpCol * 32 + (quad >> 1) * 8 + r8) * LDA + (quad & 1) * 8) * 2;
    const int g = lid >> 2, tig = lid & 3;

    float m[4][2];
    #pragma unroll
    for (int nt = 0; nt < 4; ++nt) { m[nt][0] = -INFINITY; m[nt][1] = -INFINITY; }

    for (int it = 0; it < TPC; ++it) {
        const uint32_t aB = aBase + it * 256;     // +128 windows = +256 B

        float c[4][4][4];
        #pragma unroll
        for (int mt = 0; mt < 4; ++mt)
            #pragma unroll
            for (int nt = 0; nt < 4; ++nt)
                #pragma unroll
                for (int r = 0; r < 4; ++r) c[mt][nt][r] = 0.0f;

        // Hankel ring: fr[j mod 4] = A-frag(window-block 0, k-block j)
        uint32_t fr[4][4];
        ldsm_x4(fr[0], aB);
        ldsm_x4(fr[1], aB + 32);
        ldsm_x4(fr[2], aB + 64);

        #pragma unroll
        for (int ks = 0; ks < 8; ++ks) {
            ldsm_x4(fr[(ks + 3) & 3], aB + (ks + 3) * 32);
            uint32_t bb[2][4];
            ldsm_x4(bb[0], bB + ks * 32);
            ldsm_x4(bb[1], bB + 16 * LDA * 2 + ks * 32);
            #pragma unroll
            for (int mt = 0; mt < 4; ++mt) {
                const uint32_t* a = fr[(ks + mt) & 3];   // A(mt*16, ks*16) == A(0,(ks+mt)*16)
                mma_fp16(c[mt][0], a, &bb[0][0]);
                mma_fp16(c[mt][1], a, &bb[0][2]);
                mma_fp16(c[mt][2], a, &bb[1][0]);
                mma_fp16(c[mt][3], a, &bb[1][2]);
            }
        }

        // ---- fold: scale + running max (NaN scale masks invalid windows) ----
        #pragma unroll
        for (int mt = 0; mt < 4; ++mt)
            #pragma unroll
            for (int h = 0; h < 2; ++h) {
                int row = warpRow * 64 + mt * 16 + g + h * 8;
                float sc = ws[it * 128 + row];
                #pragma unroll
                for (int nt = 0; nt < 4; ++nt)
                    #pragma unroll
                    for (int d = 0; d < 2; ++d)
                        m[nt][d] = fmaxf(m[nt][d], c[mt][nt][h * 2 + d] * sc);
            }
    }

    // ---- reduce: shfl across row-groups, smem across warpRows, atomic out ----
    #pragma unroll
    for (int nt = 0; nt < 4; ++nt)
        #pragma unroll
        for (int d = 0; d < 2; ++d) {
            float v = m[nt][d];
            #pragma unroll
            for (int off = 4; off < 32; off <<= 1)
                v = fmaxf(v, __shfl_xor_sync(0xffffffffu, v, off));
            m[nt][d] = v;
        }
    if (g == 0) {
        #pragma unroll
        for (int nt = 0; nt < 4; ++nt)
            #pragma unroll
            for (int d = 0; d < 2; ++d)
                wmax[warpRow * NF + warpCol * 32 + nt * 8 + tig * 2 + d] = m[nt][d];
    }
    __syncthreads();
    if (tid < NF) {
        float mm = fmaxf(wmax[tid], wmax[NF + tid]);
        atomicMaxFloat(&out[b * NF + tid], mm);
    }
}

extern "C" void kernel_launch(void* const* d_in, const int* in_sizes, int n_in,
                              void* d_out, int out_size) {
    const float* x  = (const float*)d_in[0];   // (256, 4096) fp32
    const float* sh = (const float*)d_in[1];   // (8, 16, 128) fp32
    float* out = (float*)d_out;                // (256, 128) fp32

    cudaFuncSetAttribute(shapelet_mma_kernel,
                         cudaFuncAttributeMaxDynamicSharedMemorySize, SMEM_DYN);

    prep_snorm_kernel<<<NF, L_LEN>>>(sh, out);
    dim3 grid(NTG, B_SZ);
    shapelet_mma_kernel<<<grid, 256, SMEM_DYN>>>(x, out);
}